// round 3
// baseline (speedup 1.0000x reference)
#include <cuda_runtime.h>

#define NN 50000
#define EE 1600000
#define GG 16
#define HH 32
#define NEG_SLOPE 0.2f

// ---------------- device scratch (static, no allocs) ----------------
__device__ __align__(128) float g_xn[NN * HH];    // transformed node feats (current layer)
__device__ __align__(128) float g_out[NN * HH];   // aggregation output / next-layer input
__device__ float g_p[EE];                         // per-edge exp(logit)
__device__ float g_s[NN];                         // per-dst softmax denominator
__device__ int   g_src[EE];
__device__ int   g_dst[EE];
__device__ __align__(16) float g_eterm[3][EE];    // per-layer edge logit contribution
__device__ __align__(16) float g_w[3][8];
__device__ float g_d[3];
__device__ float g_pool[GG * HH];
__device__ float g_cnt[GG];
__device__ int   g_is64;                          // 1 if index buffers are int64

// ---------------- dtype sniffer: int64 ids have zero high halves ----------------
__global__ void detect_kernel(const int* __restrict__ eidx_words) {
    if (threadIdx.x == 0) {
        int all_zero = 1;
        for (int i = 0; i < 64; i++) {
            if (eidx_words[2 * i + 1] != 0) { all_zero = 0; break; }
        }
        g_is64 = all_zero;
    }
}

// ---------------- tiny prep: composed edge matrices -> w_l, d_l ----------------
__global__ void prep_kernel(const float* We1, const float* be1, const float* att1,
                            const float* We2, const float* be2, const float* att2,
                            const float* We3, const float* be3, const float* att3) {
    __shared__ float M2[64], M3[64], c1[8], c2[8], c3[8];
    int t = threadIdx.x;            // 64 threads
    int i = t >> 3, j = t & 7;
    // M2 = We1 * We2 ; c2 = be1*We2 + be2
    float acc = 0.f;
    for (int k = 0; k < 8; k++) acc += We1[i * 8 + k] * We2[k * 8 + j];
    M2[t] = acc;
    if (i == 0) {
        float c = be2[j];
        for (int k = 0; k < 8; k++) c += be1[k] * We2[k * 8 + j];
        c2[j] = c;
        c1[j] = be1[j];
    }
    __syncthreads();
    // M3 = M2 * We3 ; c3 = c2*We3 + be3
    float acc3 = 0.f;
    for (int k = 0; k < 8; k++) acc3 += M2[i * 8 + k] * We3[k * 8 + j];
    M3[t] = acc3;
    if (i == 0) {
        float c = be3[j];
        for (int k = 0; k < 8; k++) c += c2[k] * We3[k * 8 + j];
        c3[j] = c;
    }
    __syncthreads();
    // w_l[k] = sum_j M_l[k][j] * ae_l[j] ; d_l = c_l . ae_l
    if (t < 24) {
        int l = t >> 3, k = t & 7;
        const float* ae = (l == 0 ? att1 : (l == 1 ? att2 : att3)) + 64;
        float w = 0.f;
        for (int jj = 0; jj < 8; jj++) {
            float m = (l == 0) ? We1[k * 8 + jj] : (l == 1 ? M2[k * 8 + jj] : M3[k * 8 + jj]);
            w += m * ae[jj];
        }
        g_w[l][k] = w;
    }
    if (t < 3) {
        const float* ae = (t == 0 ? att1 : (t == 1 ? att2 : att3)) + 64;
        const float* c = (t == 0 ? c1 : (t == 1 ? c2 : c3));
        float d = 0.f;
        for (int jj = 0; jj < 8; jj++) d += c[jj] * ae[jj];
        g_d[t] = d;
    }
    // zero pooling accumulators
    for (int idx = t; idx < GG * HH; idx += 64) g_pool[idx] = 0.f;
    if (t < GG) g_cnt[t] = 0.f;
}

// ---------------- per-edge prep: int32 indices + eterm for all 3 layers ----------------
__global__ void edge_prep_kernel(const void* __restrict__ eidxv,
                                 const float* __restrict__ ea) {
    int e = blockIdx.x * blockDim.x + threadIdx.x;
    if (e >= EE) return;
    int sn, dn;
    if (g_is64) {
        const long long* p = (const long long*)eidxv;
        sn = (int)p[e];
        dn = (int)p[EE + e];
    } else {
        const int* p = (const int*)eidxv;
        sn = p[e];
        dn = p[EE + e];
    }
    // safety clamp (wrong result beats a crash if dtype sniff were ever wrong)
    sn = min(max(sn, 0), NN - 1);
    dn = min(max(dn, 0), NN - 1);
    g_src[e] = sn;
    g_dst[e] = dn;
    const float4* ea4 = (const float4*)ea;
    float4 a0 = ea4[e * 2];
    float4 a1 = ea4[e * 2 + 1];
#pragma unroll
    for (int l = 0; l < 3; l++) {
        const float* w = g_w[l];
        float v = g_d[l]
                + a0.x * w[0] + a0.y * w[1] + a0.z * w[2] + a0.w * w[3]
                + a1.x * w[4] + a1.y * w[5] + a1.z * w[6] + a1.w * w[7];
        g_eterm[l][e] = v;
    }
}

// ---------------- node linear: xn = act(xin) @ Wn + bn ; zero out/s ----------------
template <int IN, bool RELU, bool FROM_GOUT>
__global__ void node_linear_kernel(const float* __restrict__ xin_ext,
                                   const float* __restrict__ W,
                                   const float* __restrict__ b) {
    __shared__ float sW[IN * HH];
    __shared__ float sb[HH];
    for (int i = threadIdx.x; i < IN * HH; i += blockDim.x) sW[i] = W[i];
    if (threadIdx.x < HH) sb[threadIdx.x] = b[threadIdx.x];
    __syncthreads();
    int node = blockIdx.x * blockDim.x + threadIdx.x;
    if (node >= NN) return;
    const float* xr = FROM_GOUT ? (g_out + (size_t)node * IN) : (xin_ext + (size_t)node * IN);
    float acc[HH];
#pragma unroll
    for (int h = 0; h < HH; h++) acc[h] = sb[h];
#pragma unroll
    for (int k = 0; k < IN; k++) {
        float xv = xr[k];
        if (RELU) xv = fmaxf(xv, 0.f);
#pragma unroll
        for (int h = 0; h < HH; h++) acc[h] = fmaf(xv, sW[k * HH + h], acc[h]);
    }
    float4* o = (float4*)(g_xn + (size_t)node * HH);
#pragma unroll
    for (int q = 0; q < 8; q++) o[q] = make_float4(acc[4 * q], acc[4 * q + 1], acc[4 * q + 2], acc[4 * q + 3]);
    // zero aggregation target + denominator for this layer
    float4 z = make_float4(0.f, 0.f, 0.f, 0.f);
    float4* oz = (float4*)(g_out + (size_t)node * HH);
#pragma unroll
    for (int q = 0; q < 8; q++) oz[q] = z;
    g_s[node] = 0.f;
}

// ---------------- edge pass 1: p = exp(leakyrelu(logit)) ; s[dst] += p ----------------
// 4 threads per edge, float4 gathers (coalesced: 4 lanes cover 64B halves of a row)
__global__ void edge_softmax_kernel(const float* __restrict__ att, int layer) {
    __shared__ __align__(16) float s_att[64];
    int t = threadIdx.x;
    if (t < 64) s_att[t] = att[t];
    __syncthreads();
    int e = blockIdx.x * 64 + (t >> 2);   // EE % 64 == 0, always valid
    int part = t & 3;
    int sn = g_src[e], dn = g_dst[e];
    const float4* xi = (const float4*)(g_xn + (size_t)dn * HH);
    const float4* xj = (const float4*)(g_xn + (size_t)sn * HH);
    const float4* ai = (const float4*)(s_att);
    const float4* aj = (const float4*)(s_att + 32);
    float acc;
    float4 v, a;
    v = xi[part];     a = ai[part];
    acc = fmaf(v.x, a.x, fmaf(v.y, a.y, fmaf(v.z, a.z, v.w * a.w)));
    v = xi[part + 4]; a = ai[part + 4];
    acc += fmaf(v.x, a.x, fmaf(v.y, a.y, fmaf(v.z, a.z, v.w * a.w)));
    v = xj[part];     a = aj[part];
    acc += fmaf(v.x, a.x, fmaf(v.y, a.y, fmaf(v.z, a.z, v.w * a.w)));
    v = xj[part + 4]; a = aj[part + 4];
    acc += fmaf(v.x, a.x, fmaf(v.y, a.y, fmaf(v.z, a.z, v.w * a.w)));
    // reduce over the 4 lanes of this edge
    acc += __shfl_xor_sync(0xffffffffu, acc, 1);
    acc += __shfl_xor_sync(0xffffffffu, acc, 2);
    if (part == 0) {
        float lg = acc + g_eterm[layer][e];
        lg = (lg > 0.f) ? lg : NEG_SLOPE * lg;
        float p = __expf(lg);
        g_p[e] = p;
        atomicAdd(&g_s[dn], p);
    }
}

// ---------------- vectorized global reduction ----------------
__device__ __forceinline__ void red_add_v4(float* addr, float a, float b, float c, float d) {
    asm volatile("red.global.add.v4.f32 [%0], {%1, %2, %3, %4};"
                 :: "l"(addr), "f"(a), "f"(b), "f"(c), "f"(d) : "memory");
}

// ---------------- edge pass 2: out[dst] += xn[src] * alpha ----------------
__global__ void edge_aggregate_kernel() {
    int t = threadIdx.x;
    int e = blockIdx.x * 64 + (t >> 2);
    int part = t & 3;
    int sn = g_src[e], dn = g_dst[e];
    float alpha = 0.f;
    if (part == 0) alpha = g_p[e] / (g_s[dn] + 1e-16f);
    alpha = __shfl_sync(0xffffffffu, alpha, t & 28);
    const float4* xj = (const float4*)(g_xn + (size_t)sn * HH);
    float4 v0 = xj[part];
    float4 v1 = xj[part + 4];
    float* base = g_out + (size_t)dn * HH + part * 4;
    red_add_v4(base,      v0.x * alpha, v0.y * alpha, v0.z * alpha, v0.w * alpha);
    red_add_v4(base + 16, v1.x * alpha, v1.y * alpha, v1.z * alpha, v1.w * alpha);
}

// ---------------- mean pool over sorted batch (warp-local run-length reduce) ----------------
__global__ void pool_kernel(const void* __restrict__ batchv) {
    int w = (blockIdx.x * blockDim.x + threadIdx.x) >> 5;
    int lane = threadIdx.x & 31;
    int base = w * 32;
    if (base >= NN) return;
    int is64 = g_is64;
    int nmax = min(32, NN - base);
    int myb = 0;
    if (lane < nmax) {
        if (is64) myb = (int)((const long long*)batchv)[base + lane];
        else      myb = ((const int*)batchv)[base + lane];
        myb = min(max(myb, 0), GG - 1);
    }
    float acc = 0.f, cnt = 0.f;
    int curb = __shfl_sync(0xffffffffu, myb, 0);
    for (int n = 0; n < nmax; n++) {
        int b = __shfl_sync(0xffffffffu, myb, n);
        if (b != curb) {
            atomicAdd(&g_pool[curb * HH + lane], acc);
            if (lane == 0) atomicAdd(&g_cnt[curb], cnt);
            acc = 0.f; cnt = 0.f; curb = b;
        }
        acc += g_out[(size_t)(base + n) * HH + lane];
        cnt += 1.f;
    }
    atomicAdd(&g_pool[curb * HH + lane], acc);
    if (lane == 0) atomicAdd(&g_cnt[curb], cnt);
}

// ---------------- head: out[g] = (pool[g] . Wlin) / cnt + blin ----------------
__global__ void head_kernel(const float* __restrict__ Wlin, const float* __restrict__ blin,
                            float* __restrict__ out) {
    int g = threadIdx.x >> 5;
    int lane = threadIdx.x & 31;
    if (g >= GG) return;
    float v = g_pool[g * HH + lane] * Wlin[lane];
#pragma unroll
    for (int o = 16; o > 0; o >>= 1) v += __shfl_xor_sync(0xffffffffu, v, o);
    if (lane == 0) out[g] = v / fmaxf(g_cnt[g], 1.f) + blin[0];
}

// ---------------- launch ----------------
extern "C" void kernel_launch(void* const* d_in, const int* in_sizes, int n_in,
                              void* d_out, int out_size) {
    const float* x     = (const float*)d_in[0];
    const float* ea    = (const float*)d_in[1];
    const void*  eidx  = d_in[2];
    const void*  batch = d_in[3];
    const float *Wn1 = (const float*)d_in[4],  *bn1 = (const float*)d_in[5];
    const float *We1 = (const float*)d_in[6],  *be1 = (const float*)d_in[7],  *att1 = (const float*)d_in[8];
    const float *Wn2 = (const float*)d_in[9],  *bn2 = (const float*)d_in[10];
    const float *We2 = (const float*)d_in[11], *be2 = (const float*)d_in[12], *att2 = (const float*)d_in[13];
    const float *Wn3 = (const float*)d_in[14], *bn3 = (const float*)d_in[15];
    const float *We3 = (const float*)d_in[16], *be3 = (const float*)d_in[17], *att3 = (const float*)d_in[18];
    const float *Wlin = (const float*)d_in[19], *blin = (const float*)d_in[20];
    float* out = (float*)d_out;

    const int NODE_BLOCKS = (NN + 255) / 256;
    const int EDGE_BLOCKS = EE / 64;      // 4 threads per edge, 256 threads/block

    detect_kernel<<<1, 32>>>((const int*)eidx);
    prep_kernel<<<1, 64>>>(We1, be1, att1, We2, be2, att2, We3, be3, att3);
    edge_prep_kernel<<<(EE + 255) / 256, 256>>>(eidx, ea);

    // layer 1
    node_linear_kernel<16, false, false><<<NODE_BLOCKS, 256>>>(x, Wn1, bn1);
    edge_softmax_kernel<<<EDGE_BLOCKS, 256>>>(att1, 0);
    edge_aggregate_kernel<<<EDGE_BLOCKS, 256>>>();

    // layer 2 (input = relu(g_out))
    node_linear_kernel<32, true, true><<<NODE_BLOCKS, 256>>>(nullptr, Wn2, bn2);
    edge_softmax_kernel<<<EDGE_BLOCKS, 256>>>(att2, 1);
    edge_aggregate_kernel<<<EDGE_BLOCKS, 256>>>();

    // layer 3
    node_linear_kernel<32, true, true><<<NODE_BLOCKS, 256>>>(nullptr, Wn3, bn3);
    edge_softmax_kernel<<<EDGE_BLOCKS, 256>>>(att3, 2);
    edge_aggregate_kernel<<<EDGE_BLOCKS, 256>>>();

    // pooling + head
    pool_kernel<<<NODE_BLOCKS, 256>>>(batch);
    head_kernel<<<1, 512>>>(Wlin, blin, out);
}

// round 5
// speedup vs baseline: 1.2036x; 1.2036x over previous
#include <cuda_runtime.h>

#define NN 50000
#define EE 1600000
#define GG 16
#define HH 32
#define NEG_SLOPE 0.2f

// ---------------- device scratch (static, no allocs) ----------------
__device__ __align__(128) float g_xn[NN * HH];    // transformed node feats (current layer)
__device__ __align__(128) float g_out[NN * HH];   // aggregation output / next-layer input
__device__ float g_u[NN];                         // xn . att[0:32]  (dst term)
__device__ float g_v[NN];                         // xn . att[32:64] (src term)
__device__ int   g_src[EE];                       // original-order src
__device__ int   g_dst[EE];                       // original-order dst
__device__ __align__(16) float g_eterm[3][EE];    // per-layer edge logit contribution (orig order)
__device__ int   g_csr_src[EE];                   // CSR(by dst) src ids
__device__ float g_csr_eterm[3][EE];              // CSR-order eterm per layer
__device__ int   g_deg[NN];
__device__ int   g_rowptr[NN + 1];
__device__ int   g_cursor[NN];
__device__ __align__(16) float g_w[3][8];
__device__ float g_d[3];
__device__ float g_pool[GG * HH];
__device__ float g_cnt[GG];
__device__ int   g_is64;                          // 1 if index buffers are int64

// ---------------- dtype sniffer: int64 ids have zero high halves ----------------
__global__ void detect_kernel(const int* __restrict__ eidx_words) {
    if (threadIdx.x == 0) {
        int all_zero = 1;
        for (int i = 0; i < 64; i++) {
            if (eidx_words[2 * i + 1] != 0) { all_zero = 0; break; }
        }
        g_is64 = all_zero;
    }
}

// ---------------- zero degree histogram ----------------
__global__ void zero_deg_kernel() {
    int n = blockIdx.x * blockDim.x + threadIdx.x;
    if (n < NN) g_deg[n] = 0;
}

// ---------------- tiny prep: composed edge matrices -> w_l, d_l ----------------
__global__ void prep_kernel(const float* We1, const float* be1, const float* att1,
                            const float* We2, const float* be2, const float* att2,
                            const float* We3, const float* be3, const float* att3) {
    __shared__ float M2[64], M3[64], c1[8], c2[8], c3[8];
    int t = threadIdx.x;            // 64 threads
    int i = t >> 3, j = t & 7;
    float acc = 0.f;
    for (int k = 0; k < 8; k++) acc += We1[i * 8 + k] * We2[k * 8 + j];
    M2[t] = acc;
    if (i == 0) {
        float c = be2[j];
        for (int k = 0; k < 8; k++) c += be1[k] * We2[k * 8 + j];
        c2[j] = c;
        c1[j] = be1[j];
    }
    __syncthreads();
    float acc3 = 0.f;
    for (int k = 0; k < 8; k++) acc3 += M2[i * 8 + k] * We3[k * 8 + j];
    M3[t] = acc3;
    if (i == 0) {
        float c = be3[j];
        for (int k = 0; k < 8; k++) c += c2[k] * We3[k * 8 + j];
        c3[j] = c;
    }
    __syncthreads();
    if (t < 24) {
        int l = t >> 3, k = t & 7;
        const float* ae = (l == 0 ? att1 : (l == 1 ? att2 : att3)) + 64;
        float w = 0.f;
        for (int jj = 0; jj < 8; jj++) {
            float m = (l == 0) ? We1[k * 8 + jj] : (l == 1 ? M2[k * 8 + jj] : M3[k * 8 + jj]);
            w += m * ae[jj];
        }
        g_w[l][k] = w;
    }
    if (t < 3) {
        const float* ae = (t == 0 ? att1 : (t == 1 ? att2 : att3)) + 64;
        const float* c = (t == 0 ? c1 : (t == 1 ? c2 : c3));
        float d = 0.f;
        for (int jj = 0; jj < 8; jj++) d += c[jj] * ae[jj];
        g_d[t] = d;
    }
    for (int idx = t; idx < GG * HH; idx += 64) g_pool[idx] = 0.f;
    if (t < GG) g_cnt[t] = 0.f;
}

// ---------------- per-edge prep: int32 indices + deg histogram + eterm ----------------
__global__ void edge_prep_kernel(const void* __restrict__ eidxv,
                                 const float* __restrict__ ea) {
    int e = blockIdx.x * blockDim.x + threadIdx.x;
    if (e >= EE) return;
    int sn, dn;
    if (g_is64) {
        const long long* p = (const long long*)eidxv;
        sn = (int)p[e];
        dn = (int)p[EE + e];
    } else {
        const int* p = (const int*)eidxv;
        sn = p[e];
        dn = p[EE + e];
    }
    sn = min(max(sn, 0), NN - 1);
    dn = min(max(dn, 0), NN - 1);
    g_src[e] = sn;
    g_dst[e] = dn;
    atomicAdd(&g_deg[dn], 1);
    const float4* ea4 = (const float4*)ea;
    float4 a0 = ea4[e * 2];
    float4 a1 = ea4[e * 2 + 1];
#pragma unroll
    for (int l = 0; l < 3; l++) {
        const float* w = g_w[l];
        float v = g_d[l]
                + a0.x * w[0] + a0.y * w[1] + a0.z * w[2] + a0.w * w[3]
                + a1.x * w[4] + a1.y * w[5] + a1.z * w[6] + a1.w * w[7];
        g_eterm[l][e] = v;
    }
}

// ---------------- exclusive scan of deg -> rowptr (single block) ----------------
__global__ void scan_kernel() {
    __shared__ int partial[1024];
    const int CH = (NN + 1023) / 1024;   // 49
    int t = threadIdx.x;
    int start = t * CH;
    int end = min(start + CH, NN);
    int sum = 0;
    for (int i = start; i < end; i++) sum += g_deg[i];
    partial[t] = sum;
    __syncthreads();
    // Hillis-Steele inclusive scan
    for (int off = 1; off < 1024; off <<= 1) {
        int v = (t >= off) ? partial[t - off] : 0;
        __syncthreads();
        partial[t] += v;
        __syncthreads();
    }
    int offset = (t == 0) ? 0 : partial[t - 1];
    for (int i = start; i < end; i++) {
        g_rowptr[i] = offset;
        g_cursor[i] = offset;
        offset += g_deg[i];
    }
    if (t == 1023) g_rowptr[NN] = EE;
}

// ---------------- scatter edges into CSR order ----------------
__global__ void scatter_kernel() {
    int e = blockIdx.x * blockDim.x + threadIdx.x;
    if (e >= EE) return;
    int dn = g_dst[e];
    int pos = atomicAdd(&g_cursor[dn], 1);
    g_csr_src[pos] = g_src[e];
    g_csr_eterm[0][pos] = g_eterm[0][e];
    g_csr_eterm[1][pos] = g_eterm[1][e];
    g_csr_eterm[2][pos] = g_eterm[2][e];
}

// ---------------- node linear: xn = act(xin) @ Wn + bn ; u,v scalars ----------------
template <int IN, bool RELU, bool FROM_GOUT>
__global__ void node_linear_kernel(const float* __restrict__ xin_ext,
                                   const float* __restrict__ W,
                                   const float* __restrict__ b,
                                   const float* __restrict__ att) {
    __shared__ float sW[IN * HH];
    __shared__ float sb[HH];
    __shared__ float sA[64];
    for (int i = threadIdx.x; i < IN * HH; i += blockDim.x) sW[i] = W[i];
    if (threadIdx.x < HH) sb[threadIdx.x] = b[threadIdx.x];
    if (threadIdx.x < 64) sA[threadIdx.x] = att[threadIdx.x];
    __syncthreads();
    int node = blockIdx.x * blockDim.x + threadIdx.x;
    if (node >= NN) return;
    const float* xr = FROM_GOUT ? (g_out + (size_t)node * IN) : (xin_ext + (size_t)node * IN);
    float acc[HH];
#pragma unroll
    for (int h = 0; h < HH; h++) acc[h] = sb[h];
#pragma unroll
    for (int k = 0; k < IN; k++) {
        float xv = xr[k];
        if (RELU) xv = fmaxf(xv, 0.f);
#pragma unroll
        for (int h = 0; h < HH; h++) acc[h] = fmaf(xv, sW[k * HH + h], acc[h]);
    }
    float4* o = (float4*)(g_xn + (size_t)node * HH);
#pragma unroll
    for (int q = 0; q < 8; q++) o[q] = make_float4(acc[4 * q], acc[4 * q + 1], acc[4 * q + 2], acc[4 * q + 3]);
    float u = 0.f, v = 0.f;
#pragma unroll
    for (int h = 0; h < HH; h++) {
        u = fmaf(acc[h], sA[h], u);
        v = fmaf(acc[h], sA[h + 32], v);
    }
    g_u[node] = u;
    g_v[node] = v;
}

// ---------------- fused softmax + aggregate: one warp per dst node ----------------
__global__ void edge_fused_kernel(const float* __restrict__ csr_eterm) {
    int w = (blockIdx.x * blockDim.x + threadIdx.x) >> 5;
    int lane = threadIdx.x & 31;
    if (w >= NN) return;
    int start = g_rowptr[w];
    int end = g_rowptr[w + 1];
    float u = g_u[w];
    float accv = 0.f;
    float s = 0.f;
    for (int base = start; base < end; base += 32) {
        int e = base + lane;
        bool valid = e < end;
        int sn = valid ? g_csr_src[e] : 0;
        float p = 0.f;
        if (valid) {
            float lg = u + g_v[sn] + csr_eterm[e];
            lg = (lg > 0.f) ? lg : NEG_SLOPE * lg;
            p = __expf(lg);
        }
        int cnt = min(32, end - base);
        for (int n = 0; n < cnt; n++) {
            float pn = __shfl_sync(0xffffffffu, p, n);
            int   nn = __shfl_sync(0xffffffffu, sn, n);
            accv = fmaf(pn, g_xn[(size_t)nn * HH + lane], accv);
            s += pn;
        }
    }
    g_out[(size_t)w * HH + lane] = accv / (s + 1e-16f);
}

// ---------------- mean pool over sorted batch (warp-local run-length reduce) ----------------
__global__ void pool_kernel(const void* __restrict__ batchv) {
    int w = (blockIdx.x * blockDim.x + threadIdx.x) >> 5;
    int lane = threadIdx.x & 31;
    int base = w * 32;
    if (base >= NN) return;
    int is64 = g_is64;
    int nmax = min(32, NN - base);
    int myb = 0;
    if (lane < nmax) {
        if (is64) myb = (int)((const long long*)batchv)[base + lane];
        else      myb = ((const int*)batchv)[base + lane];
        myb = min(max(myb, 0), GG - 1);
    }
    float acc = 0.f, cnt = 0.f;
    int curb = __shfl_sync(0xffffffffu, myb, 0);
    for (int n = 0; n < nmax; n++) {
        int b = __shfl_sync(0xffffffffu, myb, n);
        if (b != curb) {
            atomicAdd(&g_pool[curb * HH + lane], acc);
            if (lane == 0) atomicAdd(&g_cnt[curb], cnt);
            acc = 0.f; cnt = 0.f; curb = b;
        }
        acc += g_out[(size_t)(base + n) * HH + lane];
        cnt += 1.f;
    }
    atomicAdd(&g_pool[curb * HH + lane], acc);
    if (lane == 0) atomicAdd(&g_cnt[curb], cnt);
}

// ---------------- head ----------------
__global__ void head_kernel(const float* __restrict__ Wlin, const float* __restrict__ blin,
                            float* __restrict__ out) {
    int g = threadIdx.x >> 5;
    int lane = threadIdx.x & 31;
    if (g >= GG) return;
    float v = g_pool[g * HH + lane] * Wlin[lane];
#pragma unroll
    for (int o = 16; o > 0; o >>= 1) v += __shfl_xor_sync(0xffffffffu, v, o);
    if (lane == 0) out[g] = v / fmaxf(g_cnt[g], 1.f) + blin[0];
}

// ---------------- launch ----------------
extern "C" void kernel_launch(void* const* d_in, const int* in_sizes, int n_in,
                              void* d_out, int out_size) {
    const float* x     = (const float*)d_in[0];
    const float* ea    = (const float*)d_in[1];
    const void*  eidx  = d_in[2];
    const void*  batch = d_in[3];
    const float *Wn1 = (const float*)d_in[4],  *bn1 = (const float*)d_in[5];
    const float *We1 = (const float*)d_in[6],  *be1 = (const float*)d_in[7],  *att1 = (const float*)d_in[8];
    const float *Wn2 = (const float*)d_in[9],  *bn2 = (const float*)d_in[10];
    const float *We2 = (const float*)d_in[11], *be2 = (const float*)d_in[12], *att2 = (const float*)d_in[13];
    const float *Wn3 = (const float*)d_in[14], *bn3 = (const float*)d_in[15];
    const float *We3 = (const float*)d_in[16], *be3 = (const float*)d_in[17], *att3 = (const float*)d_in[18];
    const float *Wlin = (const float*)d_in[19], *blin = (const float*)d_in[20];
    float* out = (float*)d_out;

    const int NODE_BLOCKS = (NN + 255) / 256;
    const int WARP_BLOCKS = (NN * 32 + 255) / 256;   // one warp per node

    float* et0; cudaGetSymbolAddress((void**)&et0, g_csr_eterm);

    detect_kernel<<<1, 32>>>((const int*)eidx);
    zero_deg_kernel<<<NODE_BLOCKS, 256>>>();
    prep_kernel<<<1, 64>>>(We1, be1, att1, We2, be2, att2, We3, be3, att3);
    edge_prep_kernel<<<(EE + 255) / 256, 256>>>(eidx, ea);
    scan_kernel<<<1, 1024>>>();
    scatter_kernel<<<(EE + 255) / 256, 256>>>();

    // layer 1
    node_linear_kernel<16, false, false><<<NODE_BLOCKS, 256>>>(x, Wn1, bn1, att1);
    edge_fused_kernel<<<WARP_BLOCKS, 256>>>(et0);
    // layer 2
    node_linear_kernel<32, true, true><<<NODE_BLOCKS, 256>>>(nullptr, Wn2, bn2, att2);
    edge_fused_kernel<<<WARP_BLOCKS, 256>>>(et0 + EE);
    // layer 3
    node_linear_kernel<32, true, true><<<NODE_BLOCKS, 256>>>(nullptr, Wn3, bn3, att3);
    edge_fused_kernel<<<WARP_BLOCKS, 256>>>(et0 + 2 * EE);

    // pooling + head
    pool_kernel<<<NODE_BLOCKS, 256>>>(batch);
    head_kernel<<<1, 512>>>(Wlin, blin, out);
}

// round 7
// speedup vs baseline: 1.3274x; 1.1029x over previous
#include <cuda_runtime.h>

#define NN 50000
#define EE 1600000
#define GG 16
#define HH 32
#define NEG_SLOPE 0.2f

// ---------------- device scratch (static, no allocs) ----------------
__device__ __align__(128) float g_xn[NN * HH];    // transformed node feats (current layer)
__device__ __align__(128) float g_out[NN * HH];   // aggregation output / next-layer input
__device__ float g_u[NN];                         // xn . att[0:32]  (dst term)
__device__ float g_v[NN];                         // xn . att[32:64] (src term)
__device__ __align__(16) float4 g_csr[EE];        // {src_bits, et1, et2, et3} grouped by dst
__device__ int   g_deg[NN];
__device__ int   g_rowptr[NN + 1];
__device__ int   g_cursor[NN];
__device__ __align__(16) float g_w[3][8];
__device__ float g_d[3];
__device__ float g_pool[GG * HH];
__device__ float g_cnt[GG];
__device__ int   g_is64;                          // 1 if index buffers are int64

// ---------------- dtype sniffer: int64 ids have zero high halves ----------------
__global__ void detect_kernel(const int* __restrict__ eidx_words) {
    if (threadIdx.x == 0) {
        int all_zero = 1;
        for (int i = 0; i < 64; i++) {
            if (eidx_words[2 * i + 1] != 0) { all_zero = 0; break; }
        }
        g_is64 = all_zero;
    }
}

// ---------------- zero degree histogram ----------------
__global__ void zero_deg_kernel() {
    int n = blockIdx.x * blockDim.x + threadIdx.x;
    if (n < NN) g_deg[n] = 0;
}

// ---------------- tiny prep: composed edge matrices -> w_l, d_l ----------------
__global__ void prep_kernel(const float* We1, const float* be1, const float* att1,
                            const float* We2, const float* be2, const float* att2,
                            const float* We3, const float* be3, const float* att3) {
    __shared__ float M2[64], M3[64], c1[8], c2[8], c3[8];
    int t = threadIdx.x;            // 64 threads
    int i = t >> 3, j = t & 7;
    float acc = 0.f;
    for (int k = 0; k < 8; k++) acc += We1[i * 8 + k] * We2[k * 8 + j];
    M2[t] = acc;
    if (i == 0) {
        float c = be2[j];
        for (int k = 0; k < 8; k++) c += be1[k] * We2[k * 8 + j];
        c2[j] = c;
        c1[j] = be1[j];
    }
    __syncthreads();
    float acc3 = 0.f;
    for (int k = 0; k < 8; k++) acc3 += M2[i * 8 + k] * We3[k * 8 + j];
    M3[t] = acc3;
    if (i == 0) {
        float c = be3[j];
        for (int k = 0; k < 8; k++) c += c2[k] * We3[k * 8 + j];
        c3[j] = c;
    }
    __syncthreads();
    if (t < 24) {
        int l = t >> 3, k = t & 7;
        const float* ae = (l == 0 ? att1 : (l == 1 ? att2 : att3)) + 64;
        float w = 0.f;
        for (int jj = 0; jj < 8; jj++) {
            float m = (l == 0) ? We1[k * 8 + jj] : (l == 1 ? M2[k * 8 + jj] : M3[k * 8 + jj]);
            w += m * ae[jj];
        }
        g_w[l][k] = w;
    }
    if (t < 3) {
        const float* ae = (t == 0 ? att1 : (t == 1 ? att2 : att3)) + 64;
        const float* c = (t == 0 ? c1 : (t == 1 ? c2 : c3));
        float d = 0.f;
        for (int jj = 0; jj < 8; jj++) d += c[jj] * ae[jj];
        g_d[t] = d;
    }
    for (int idx = t; idx < GG * HH; idx += 64) g_pool[idx] = 0.f;
    if (t < GG) g_cnt[t] = 0.f;
}

// ---------------- degree histogram (dst only) ----------------
__global__ void deg_kernel(const void* __restrict__ eidxv) {
    int e = blockIdx.x * blockDim.x + threadIdx.x;
    if (e >= EE) return;
    int dn;
    if (g_is64) dn = (int)((const long long*)eidxv)[EE + e];
    else        dn = ((const int*)eidxv)[EE + e];
    dn = min(max(dn, 0), NN - 1);
    atomicAdd(&g_deg[dn], 1);
}

// ---------------- exclusive scan of deg -> rowptr (single block) ----------------
__global__ void scan_kernel() {
    __shared__ int partial[1024];
    const int CH = (NN + 1023) / 1024;   // 49
    int t = threadIdx.x;
    int start = t * CH;
    int end = min(start + CH, NN);
    int sum = 0;
    for (int i = start; i < end; i++) sum += g_deg[i];
    partial[t] = sum;
    __syncthreads();
    for (int off = 1; off < 1024; off <<= 1) {
        int v = (t >= off) ? partial[t - off] : 0;
        __syncthreads();
        partial[t] += v;
        __syncthreads();
    }
    int offset = (t == 0) ? 0 : partial[t - 1];
    for (int i = start; i < end; i++) {
        g_rowptr[i] = offset;
        g_cursor[i] = offset;
        offset += g_deg[i];
    }
    if (t == 1023) g_rowptr[NN] = EE;
}

// ---------------- fused eterm + scatter: one float4 store per edge ----------------
__global__ void scatter_fused_kernel(const void* __restrict__ eidxv,
                                     const float* __restrict__ ea) {
    int e = blockIdx.x * blockDim.x + threadIdx.x;
    if (e >= EE) return;
    int sn, dn;
    if (g_is64) {
        const long long* p = (const long long*)eidxv;
        sn = (int)p[e];
        dn = (int)p[EE + e];
    } else {
        const int* p = (const int*)eidxv;
        sn = p[e];
        dn = p[EE + e];
    }
    sn = min(max(sn, 0), NN - 1);
    dn = min(max(dn, 0), NN - 1);
    const float4* ea4 = (const float4*)ea;
    float4 a0 = ea4[e * 2];
    float4 a1 = ea4[e * 2 + 1];
    float et[3];
#pragma unroll
    for (int l = 0; l < 3; l++) {
        const float* w = g_w[l];
        et[l] = g_d[l]
              + a0.x * w[0] + a0.y * w[1] + a0.z * w[2] + a0.w * w[3]
              + a1.x * w[4] + a1.y * w[5] + a1.z * w[6] + a1.w * w[7];
    }
    int pos = atomicAdd(&g_cursor[dn], 1);
    g_csr[pos] = make_float4(__int_as_float(sn), et[0], et[1], et[2]);
}

// ---------------- node linear: smem-staged input, xn = act(xin) @ Wn + bn ----------------
template <int IN, bool RELU, bool FROM_GOUT>
__global__ void node_linear_kernel(const float* __restrict__ xin_ext,
                                   const float* __restrict__ W,
                                   const float* __restrict__ b,
                                   const float* __restrict__ att) {
    __shared__ float sW[IN * HH];
    __shared__ float sb[HH];
    __shared__ float sA[64];
    __shared__ float sX[256 * (IN + 1)];
    int tid = threadIdx.x;
    for (int i = tid; i < IN * HH; i += blockDim.x) sW[i] = W[i];
    if (tid < HH) sb[tid] = b[tid];
    if (tid < 64) sA[tid] = att[tid];
    int base = blockIdx.x * 256;
    int nvalid = min(256, NN - base);
    const float* src = FROM_GOUT ? g_out : xin_ext;
    // coalesced block load into padded smem
    for (int i = tid; i < nvalid * IN; i += 256) {
        int nl = i / IN;
        int k = i - nl * IN;
        sX[nl * (IN + 1) + k] = src[(size_t)base * IN + i];
    }
    __syncthreads();
    int node = base + tid;
    if (tid >= nvalid) return;
    const float* xr = sX + tid * (IN + 1);
    float acc[HH];
#pragma unroll
    for (int h = 0; h < HH; h++) acc[h] = sb[h];
#pragma unroll
    for (int k = 0; k < IN; k++) {
        float xv = xr[k];
        if (RELU) xv = fmaxf(xv, 0.f);
#pragma unroll
        for (int h = 0; h < HH; h++) acc[h] = fmaf(xv, sW[k * HH + h], acc[h]);
    }
    float4* o = (float4*)(g_xn + (size_t)node * HH);
#pragma unroll
    for (int q = 0; q < 8; q++) o[q] = make_float4(acc[4 * q], acc[4 * q + 1], acc[4 * q + 2], acc[4 * q + 3]);
    float u = 0.f, v = 0.f;
#pragma unroll
    for (int h = 0; h < HH; h++) {
        u = fmaf(acc[h], sA[h], u);
        v = fmaf(acc[h], sA[h + 32], v);
    }
    g_u[node] = u;
    g_v[node] = v;
}

// ---------------- fused softmax + aggregate: one warp per dst node ----------------
template <int L>
__global__ void edge_fused_kernel() {
    int w = (blockIdx.x * blockDim.x + threadIdx.x) >> 5;
    int lane = threadIdx.x & 31;
    if (w >= NN) return;
    int start = g_rowptr[w];
    int end = g_rowptr[w + 1];
    float u = g_u[w];
    float accv = 0.f;
    float s = 0.f;
    for (int base = start; base < end; base += 32) {
        int e = base + lane;
        int sn = 0;
        float p = 0.f;
        if (e < end) {
            float4 q = g_csr[e];
            sn = __float_as_int(q.x);
            float et = (L == 0) ? q.y : (L == 1) ? q.z : q.w;
            float lg = u + g_v[sn] + et;
            lg = (lg > 0.f) ? lg : NEG_SLOPE * lg;
            p = __expf(lg);
        }
        int cnt = min(32, end - base);
        for (int n = 0; n < cnt; n++) {
            float pn = __shfl_sync(0xffffffffu, p, n);
            int   nn = __shfl_sync(0xffffffffu, sn, n);
            accv = fmaf(pn, g_xn[(size_t)nn * HH + lane], accv);
            s += pn;
        }
    }
    g_out[(size_t)w * HH + lane] = accv / (s + 1e-16f);
}

// ---------------- mean pool over sorted batch (warp-local run-length reduce) ----------------
__global__ void pool_kernel(const void* __restrict__ batchv) {
    int w = (blockIdx.x * blockDim.x + threadIdx.x) >> 5;
    int lane = threadIdx.x & 31;
    int base = w * 32;
    if (base >= NN) return;
    int is64 = g_is64;
    int nmax = min(32, NN - base);
    int myb = 0;
    if (lane < nmax) {
        if (is64) myb = (int)((const long long*)batchv)[base + lane];
        else      myb = ((const int*)batchv)[base + lane];
        myb = min(max(myb, 0), GG - 1);
    }
    float acc = 0.f, cnt = 0.f;
    int curb = __shfl_sync(0xffffffffu, myb, 0);
    for (int n = 0; n < nmax; n++) {
        int b = __shfl_sync(0xffffffffu, myb, n);
        if (b != curb) {
            atomicAdd(&g_pool[curb * HH + lane], acc);
            if (lane == 0) atomicAdd(&g_cnt[curb], cnt);
            acc = 0.f; cnt = 0.f; curb = b;
        }
        acc += g_out[(size_t)(base + n) * HH + lane];
        cnt += 1.f;
    }
    atomicAdd(&g_pool[curb * HH + lane], acc);
    if (lane == 0) atomicAdd(&g_cnt[curb], cnt);
}

// ---------------- head ----------------
__global__ void head_kernel(const float* __restrict__ Wlin, const float* __restrict__ blin,
                            float* __restrict__ out) {
    int g = threadIdx.x >> 5;
    int lane = threadIdx.x & 31;
    if (g >= GG) return;
    float v = g_pool[g * HH + lane] * Wlin[lane];
#pragma unroll
    for (int o = 16; o > 0; o >>= 1) v += __shfl_xor_sync(0xffffffffu, v, o);
    if (lane == 0) out[g] = v / fmaxf(g_cnt[g], 1.f) + blin[0];
}

// ---------------- launch ----------------
extern "C" void kernel_launch(void* const* d_in, const int* in_sizes, int n_in,
                              void* d_out, int out_size) {
    const float* x     = (const float*)d_in[0];
    const float* ea    = (const float*)d_in[1];
    const void*  eidx  = d_in[2];
    const void*  batch = d_in[3];
    const float *Wn1 = (const float*)d_in[4],  *bn1 = (const float*)d_in[5];
    const float *att1 = (const float*)d_in[8];
    const float *Wn2 = (const float*)d_in[9],  *bn2 = (const float*)d_in[10];
    const float *att2 = (const float*)d_in[13];
    const float *Wn3 = (const float*)d_in[14], *bn3 = (const float*)d_in[15];
    const float *att3 = (const float*)d_in[18];
    const float *We1 = (const float*)d_in[6],  *be1 = (const float*)d_in[7];
    const float *We2 = (const float*)d_in[11], *be2 = (const float*)d_in[12];
    const float *We3 = (const float*)d_in[16], *be3 = (const float*)d_in[17];
    const float *Wlin = (const float*)d_in[19], *blin = (const float*)d_in[20];
    float* out = (float*)d_out;

    const int NODE_BLOCKS = (NN + 255) / 256;
    const int WARP_BLOCKS = (NN * 32 + 255) / 256;   // one warp per node
    const int EDGE_BLOCKS = (EE + 255) / 256;

    detect_kernel<<<1, 32>>>((const int*)eidx);
    zero_deg_kernel<<<NODE_BLOCKS, 256>>>();
    prep_kernel<<<1, 64>>>(We1, be1, att1, We2, be2, att2, We3, be3, att3);
    deg_kernel<<<EDGE_BLOCKS, 256>>>(eidx);
    scan_kernel<<<1, 1024>>>();
    scatter_fused_kernel<<<EDGE_BLOCKS, 256>>>(eidx, ea);

    // layer 1
    node_linear_kernel<16, false, false><<<NODE_BLOCKS, 256>>>(x, Wn1, bn1, att1);
    edge_fused_kernel<0><<<WARP_BLOCKS, 256>>>();
    // layer 2
    node_linear_kernel<32, true, true><<<NODE_BLOCKS, 256>>>(nullptr, Wn2, bn2, att2);
    edge_fused_kernel<1><<<WARP_BLOCKS, 256>>>();
    // layer 3
    node_linear_kernel<32, true, true><<<NODE_BLOCKS, 256>>>(nullptr, Wn3, bn3, att3);
    edge_fused_kernel<2><<<WARP_BLOCKS, 256>>>();

    // pooling + head
    pool_kernel<<<NODE_BLOCKS, 256>>>(batch);
    head_kernel<<<1, 512>>>(Wlin, blin, out);
}

// round 8
// speedup vs baseline: 1.9214x; 1.4474x over previous
#include <cuda_runtime.h>

#define NN 50000
#define EE 1600000
#define GG 16
#define HH 32
#define NEG_SLOPE 0.2f
#define NB 49   // scan blocks: ceil(50000/1024)

// ---------------- device scratch (static, no allocs) ----------------
__device__ __align__(128) float g_xn[NN * HH];
__device__ __align__(128) float g_out[NN * HH];
__device__ float g_u[NN];
__device__ float g_v[NN];
__device__ __align__(16) float4 g_csr[EE];        // {src_bits, et1, et2, et3} grouped by dst
__device__ int   g_deg[NN];
__device__ int   g_rowptr[NN + 1];
__device__ int   g_cursor[NN];
__device__ int   g_bsum[NB];
__device__ int   g_boff[NB];
__device__ __align__(16) float g_w[3][8];
__device__ float g_d[3];
__device__ float g_pool[GG * HH];
__device__ float g_cnt[GG];
__device__ int   g_is64;

// ---------------- detect dtype + zero deg ----------------
__global__ void detect_zero_kernel(const int* __restrict__ eidx_words) {
    int n = blockIdx.x * blockDim.x + threadIdx.x;
    if (n < NN) g_deg[n] = 0;
    if (n == 0) {
        int all_zero = 1;
        for (int i = 0; i < 64; i++) {
            if (eidx_words[2 * i + 1] != 0) { all_zero = 0; break; }
        }
        g_is64 = all_zero;
    }
}

// ---------------- tiny prep: composed edge matrices -> w_l, d_l ----------------
__global__ void prep_kernel(const float* We1, const float* be1, const float* att1,
                            const float* We2, const float* be2, const float* att2,
                            const float* We3, const float* be3, const float* att3) {
    __shared__ float M2[64], M3[64], c1[8], c2[8], c3[8];
    int t = threadIdx.x;            // 64 threads
    int i = t >> 3, j = t & 7;
    float acc = 0.f;
    for (int k = 0; k < 8; k++) acc += We1[i * 8 + k] * We2[k * 8 + j];
    M2[t] = acc;
    if (i == 0) {
        float c = be2[j];
        for (int k = 0; k < 8; k++) c += be1[k] * We2[k * 8 + j];
        c2[j] = c;
        c1[j] = be1[j];
    }
    __syncthreads();
    float acc3 = 0.f;
    for (int k = 0; k < 8; k++) acc3 += M2[i * 8 + k] * We3[k * 8 + j];
    M3[t] = acc3;
    if (i == 0) {
        float c = be3[j];
        for (int k = 0; k < 8; k++) c += c2[k] * We3[k * 8 + j];
        c3[j] = c;
    }
    __syncthreads();
    if (t < 24) {
        int l = t >> 3, k = t & 7;
        const float* ae = (l == 0 ? att1 : (l == 1 ? att2 : att3)) + 64;
        float w = 0.f;
        for (int jj = 0; jj < 8; jj++) {
            float m = (l == 0) ? We1[k * 8 + jj] : (l == 1 ? M2[k * 8 + jj] : M3[k * 8 + jj]);
            w += m * ae[jj];
        }
        g_w[l][k] = w;
    }
    if (t < 3) {
        const float* ae = (t == 0 ? att1 : (t == 1 ? att2 : att3)) + 64;
        const float* c = (t == 0 ? c1 : (t == 1 ? c2 : c3));
        float d = 0.f;
        for (int jj = 0; jj < 8; jj++) d += c[jj] * ae[jj];
        g_d[t] = d;
    }
    for (int idx = t; idx < GG * HH; idx += 64) g_pool[idx] = 0.f;
    if (t < GG) g_cnt[t] = 0.f;
}

// ---------------- degree histogram: 4 edges per thread ----------------
__global__ void deg_kernel(const void* __restrict__ eidxv) {
    int t = blockIdx.x * blockDim.x + threadIdx.x;
    if (t * 4 >= EE) return;
    int d[4];
    if (g_is64) {
        const longlong4* p = (const longlong4*)((const long long*)eidxv + EE);
        longlong4 q = p[t];
        d[0] = (int)q.x; d[1] = (int)q.y; d[2] = (int)q.z; d[3] = (int)q.w;
    } else {
        const int4* p = (const int4*)((const int*)eidxv + EE);
        int4 q = p[t];
        d[0] = q.x; d[1] = q.y; d[2] = q.z; d[3] = q.w;
    }
#pragma unroll
    for (int i = 0; i < 4; i++) {
        int dn = min(max(d[i], 0), NN - 1);
        atomicAdd(&g_deg[dn], 1);
    }
}

// ---------------- multi-block scan: A (block sums), B (scan sums), C (local scan) ----
__global__ void scanA_kernel() {
    __shared__ int sh[1024];
    int i = blockIdx.x * 1024 + threadIdx.x;
    int v = (i < NN) ? g_deg[i] : 0;
    sh[threadIdx.x] = v;
    __syncthreads();
    for (int off = 512; off > 0; off >>= 1) {
        if (threadIdx.x < off) sh[threadIdx.x] += sh[threadIdx.x + off];
        __syncthreads();
    }
    if (threadIdx.x == 0) g_bsum[blockIdx.x] = sh[0];
}
__global__ void scanB_kernel() {
    __shared__ int sh[64];
    int t = threadIdx.x;
    int v = (t < NB) ? g_bsum[t] : 0;
    sh[t] = v;
    __syncthreads();
    for (int off = 1; off < 64; off <<= 1) {
        int x = (t >= off) ? sh[t - off] : 0;
        __syncthreads();
        sh[t] += x;
        __syncthreads();
    }
    if (t < NB) g_boff[t] = sh[t] - v;   // exclusive
}
__global__ void scanC_kernel() {
    __shared__ int sh[1024];
    int i = blockIdx.x * 1024 + threadIdx.x;
    int v = (i < NN) ? g_deg[i] : 0;
    sh[threadIdx.x] = v;
    __syncthreads();
    for (int off = 1; off < 1024; off <<= 1) {
        int x = (threadIdx.x >= off) ? sh[threadIdx.x - off] : 0;
        __syncthreads();
        sh[threadIdx.x] += x;
        __syncthreads();
    }
    int excl = sh[threadIdx.x] - v + g_boff[blockIdx.x];
    if (i < NN) { g_rowptr[i] = excl; g_cursor[i] = excl; }
    if (i == 0) g_rowptr[NN] = EE;
}

// ---------------- fused eterm + scatter: 2 edges per thread ----------------
__global__ void scatter_fused_kernel(const void* __restrict__ eidxv,
                                     const float* __restrict__ ea) {
    int t = blockIdx.x * blockDim.x + threadIdx.x;
    if (t * 2 >= EE) return;
    int sn[2], dn[2];
    if (g_is64) {
        const longlong2* ps = (const longlong2*)eidxv;
        const longlong2* pd = (const longlong2*)((const long long*)eidxv + EE);
        longlong2 qs = ps[t], qd = pd[t];
        sn[0] = (int)qs.x; sn[1] = (int)qs.y;
        dn[0] = (int)qd.x; dn[1] = (int)qd.y;
    } else {
        const int2* ps = (const int2*)eidxv;
        const int2* pd = (const int2*)((const int*)eidxv + EE);
        int2 qs = ps[t], qd = pd[t];
        sn[0] = qs.x; sn[1] = qs.y;
        dn[0] = qd.x; dn[1] = qd.y;
    }
    const float4* ea4 = (const float4*)ea;
#pragma unroll
    for (int k = 0; k < 2; k++) {
        int e = t * 2 + k;
        int s = min(max(sn[k], 0), NN - 1);
        int d = min(max(dn[k], 0), NN - 1);
        float4 a0 = ea4[e * 2];
        float4 a1 = ea4[e * 2 + 1];
        float et[3];
#pragma unroll
        for (int l = 0; l < 3; l++) {
            const float* w = g_w[l];
            et[l] = g_d[l]
                  + a0.x * w[0] + a0.y * w[1] + a0.z * w[2] + a0.w * w[3]
                  + a1.x * w[4] + a1.y * w[5] + a1.z * w[6] + a1.w * w[7];
        }
        int pos = atomicAdd(&g_cursor[d], 1);
        g_csr[pos] = make_float4(__int_as_float(s), et[0], et[1], et[2]);
    }
}

// ---------------- node linear: smem-staged input ----------------
template <int IN, bool RELU, bool FROM_GOUT>
__global__ void node_linear_kernel(const float* __restrict__ xin_ext,
                                   const float* __restrict__ W,
                                   const float* __restrict__ b,
                                   const float* __restrict__ att) {
    __shared__ float sW[IN * HH];
    __shared__ float sb[HH];
    __shared__ float sA[64];
    __shared__ float sX[256 * (IN + 1)];
    int tid = threadIdx.x;
    for (int i = tid; i < IN * HH; i += blockDim.x) sW[i] = W[i];
    if (tid < HH) sb[tid] = b[tid];
    if (tid < 64) sA[tid] = att[tid];
    int base = blockIdx.x * 256;
    int nvalid = min(256, NN - base);
    const float* src = FROM_GOUT ? g_out : xin_ext;
    for (int i = tid; i < nvalid * IN; i += 256) {
        int nl = i / IN;
        int k = i - nl * IN;
        sX[nl * (IN + 1) + k] = src[(size_t)base * IN + i];
    }
    __syncthreads();
    int node = base + tid;
    if (tid >= nvalid) return;
    const float* xr = sX + tid * (IN + 1);
    float acc[HH];
#pragma unroll
    for (int h = 0; h < HH; h++) acc[h] = sb[h];
#pragma unroll
    for (int k = 0; k < IN; k++) {
        float xv = xr[k];
        if (RELU) xv = fmaxf(xv, 0.f);
#pragma unroll
        for (int h = 0; h < HH; h++) acc[h] = fmaf(xv, sW[k * HH + h], acc[h]);
    }
    float4* o = (float4*)(g_xn + (size_t)node * HH);
#pragma unroll
    for (int q = 0; q < 8; q++) o[q] = make_float4(acc[4 * q], acc[4 * q + 1], acc[4 * q + 2], acc[4 * q + 3]);
    float u = 0.f, v = 0.f;
#pragma unroll
    for (int h = 0; h < HH; h++) {
        u = fmaf(acc[h], sA[h], u);
        v = fmaf(acc[h], sA[h + 32], v);
    }
    g_u[node] = u;
    g_v[node] = v;
}

// ---------------- fused softmax + aggregate: one warp per dst node ----------------
// Phase 1: 32 lanes compute p for 32 edges, stage {sn,p} in smem.
// Phase 2: 8 edges in parallel, 4 lanes each take a 16B slice of the src row.
template <int L>
__global__ void edge_fused_kernel() {
    __shared__ __align__(8) float2 sE[8][32];
    int wib = threadIdx.x >> 5;
    int w = (blockIdx.x * blockDim.x + threadIdx.x) >> 5;
    int lane = threadIdx.x & 31;
    if (w >= NN) return;
    int start = g_rowptr[w];
    int end = g_rowptr[w + 1];
    float u = g_u[w];
    int part = lane & 3, grp = lane >> 2;
    float acc[8] = {0.f, 0.f, 0.f, 0.f, 0.f, 0.f, 0.f, 0.f};
    float s = 0.f;
    for (int base = start; base < end; base += 32) {
        int e = base + lane;
        float p = 0.f; int sn = 0;
        if (e < end) {
            float4 q = g_csr[e];
            sn = __float_as_int(q.x);
            float et = (L == 0) ? q.y : (L == 1) ? q.z : q.w;
            float lg = u + g_v[sn] + et;
            lg = (lg > 0.f) ? lg : NEG_SLOPE * lg;
            p = __expf(lg);
        }
        sE[wib][lane] = make_float2(__int_as_float(sn), p);
        __syncwarp();
        int cnt = min(32, end - base);
        for (int j = grp; j < cnt; j += 8) {
            float2 sp = sE[wib][j];
            int snn = __float_as_int(sp.x);
            float pp = sp.y;
            const float4* row = (const float4*)(g_xn + (size_t)snn * HH);
            float4 v0 = row[part];
            float4 v1 = row[part + 4];
            acc[0] = fmaf(pp, v0.x, acc[0]);
            acc[1] = fmaf(pp, v0.y, acc[1]);
            acc[2] = fmaf(pp, v0.z, acc[2]);
            acc[3] = fmaf(pp, v0.w, acc[3]);
            acc[4] = fmaf(pp, v1.x, acc[4]);
            acc[5] = fmaf(pp, v1.y, acc[5]);
            acc[6] = fmaf(pp, v1.z, acc[6]);
            acc[7] = fmaf(pp, v1.w, acc[7]);
            s += pp;
        }
        __syncwarp();
    }
    // reduce across the 8 groups (same part, different grp)
#pragma unroll
    for (int off = 16; off >= 4; off >>= 1) {
#pragma unroll
        for (int i = 0; i < 8; i++) acc[i] += __shfl_down_sync(0xffffffffu, acc[i], off);
        s += __shfl_down_sync(0xffffffffu, s, off);
    }
    if (grp == 0) {
        float inv = 1.f / (s + 1e-16f);
        float4* o = (float4*)(g_out + (size_t)w * HH);
        o[part]     = make_float4(acc[0] * inv, acc[1] * inv, acc[2] * inv, acc[3] * inv);
        o[part + 4] = make_float4(acc[4] * inv, acc[5] * inv, acc[6] * inv, acc[7] * inv);
    }
}

// ---------------- mean pool over sorted batch ----------------
__global__ void pool_kernel(const void* __restrict__ batchv) {
    int w = (blockIdx.x * blockDim.x + threadIdx.x) >> 5;
    int lane = threadIdx.x & 31;
    int base = w * 32;
    if (base >= NN) return;
    int is64 = g_is64;
    int nmax = min(32, NN - base);
    int myb = 0;
    if (lane < nmax) {
        if (is64) myb = (int)((const long long*)batchv)[base + lane];
        else      myb = ((const int*)batchv)[base + lane];
        myb = min(max(myb, 0), GG - 1);
    }
    float acc = 0.f, cnt = 0.f;
    int curb = __shfl_sync(0xffffffffu, myb, 0);
    for (int n = 0; n < nmax; n++) {
        int b = __shfl_sync(0xffffffffu, myb, n);
        if (b != curb) {
            atomicAdd(&g_pool[curb * HH + lane], acc);
            if (lane == 0) atomicAdd(&g_cnt[curb], cnt);
            acc = 0.f; cnt = 0.f; curb = b;
        }
        acc += g_out[(size_t)(base + n) * HH + lane];
        cnt += 1.f;
    }
    atomicAdd(&g_pool[curb * HH + lane], acc);
    if (lane == 0) atomicAdd(&g_cnt[curb], cnt);
}

// ---------------- head ----------------
__global__ void head_kernel(const float* __restrict__ Wlin, const float* __restrict__ blin,
                            float* __restrict__ out) {
    int g = threadIdx.x >> 5;
    int lane = threadIdx.x & 31;
    if (g >= GG) return;
    float v = g_pool[g * HH + lane] * Wlin[lane];
#pragma unroll
    for (int o = 16; o > 0; o >>= 1) v += __shfl_xor_sync(0xffffffffu, v, o);
    if (lane == 0) out[g] = v / fmaxf(g_cnt[g], 1.f) + blin[0];
}

// ---------------- launch ----------------
extern "C" void kernel_launch(void* const* d_in, const int* in_sizes, int n_in,
                              void* d_out, int out_size) {
    const float* x     = (const float*)d_in[0];
    const float* ea    = (const float*)d_in[1];
    const void*  eidx  = d_in[2];
    const void*  batch = d_in[3];
    const float *Wn1 = (const float*)d_in[4],  *bn1 = (const float*)d_in[5];
    const float *We1 = (const float*)d_in[6],  *be1 = (const float*)d_in[7],  *att1 = (const float*)d_in[8];
    const float *Wn2 = (const float*)d_in[9],  *bn2 = (const float*)d_in[10];
    const float *We2 = (const float*)d_in[11], *be2 = (const float*)d_in[12], *att2 = (const float*)d_in[13];
    const float *Wn3 = (const float*)d_in[14], *bn3 = (const float*)d_in[15];
    const float *We3 = (const float*)d_in[16], *be3 = (const float*)d_in[17], *att3 = (const float*)d_in[18];
    const float *Wlin = (const float*)d_in[19], *blin = (const float*)d_in[20];
    float* out = (float*)d_out;

    const int NODE_BLOCKS = (NN + 255) / 256;
    const int WARP_BLOCKS = (NN * 32 + 255) / 256;

    detect_zero_kernel<<<NODE_BLOCKS, 256>>>((const int*)eidx);
    prep_kernel<<<1, 64>>>(We1, be1, att1, We2, be2, att2, We3, be3, att3);
    deg_kernel<<<(EE / 4 + 255) / 256, 256>>>(eidx);
    scanA_kernel<<<NB, 1024>>>();
    scanB_kernel<<<1, 64>>>();
    scanC_kernel<<<NB, 1024>>>();
    scatter_fused_kernel<<<(EE / 2 + 255) / 256, 256>>>(eidx, ea);

    // layer 1
    node_linear_kernel<16, false, false><<<NODE_BLOCKS, 256>>>(x, Wn1, bn1, att1);
    edge_fused_kernel<0><<<WARP_BLOCKS, 256>>>();
    // layer 2
    node_linear_kernel<32, true, true><<<NODE_BLOCKS, 256>>>(nullptr, Wn2, bn2, att2);
    edge_fused_kernel<1><<<WARP_BLOCKS, 256>>>();
    // layer 3
    node_linear_kernel<32, true, true><<<NODE_BLOCKS, 256>>>(nullptr, Wn3, bn3, att3);
    edge_fused_kernel<2><<<WARP_BLOCKS, 256>>>();

    // pooling + head
    pool_kernel<<<NODE_BLOCKS, 256>>>(batch);
    head_kernel<<<1, 512>>>(Wlin, blin, out);
}

// round 9
// speedup vs baseline: 1.9841x; 1.0327x over previous
#include <cuda_runtime.h>
#include <cuda_fp16.h>

#define NN 50000
#define EE 1600000
#define GG 16
#define HH 32
#define NEG_SLOPE 0.2f
#define NB 49   // scan blocks: ceil(50000/1024)

// ---------------- device scratch (static, no allocs) ----------------
__device__ __align__(128) __half2 g_xnh[NN * 16];   // fp16 node feats (gather target)
__device__ __align__(128) float g_out[NN * HH];     // fp32 layer output / next input
__device__ float g_u[NN];
__device__ float g_v[NN];
__device__ __align__(16) float4 g_csr[EE];          // {src_bits, et1, et2, et3} grouped by dst
__device__ int   g_deg[NN];
__device__ int   g_rowptr[NN + 1];
__device__ int   g_cursor[NN];
__device__ int   g_bsum[NB];
__device__ int   g_boff[NB];
__device__ __align__(16) float g_w[3][8];
__device__ float g_d[3];
__device__ float g_pool[GG * HH];
__device__ float g_cnt[GG];
__device__ int   g_is64;

// ---------------- detect dtype + zero deg ----------------
__global__ void detect_zero_kernel(const int* __restrict__ eidx_words) {
    int n = blockIdx.x * blockDim.x + threadIdx.x;
    if (n < NN) g_deg[n] = 0;
    if (n == 0) {
        int all_zero = 1;
        for (int i = 0; i < 64; i++) {
            if (eidx_words[2 * i + 1] != 0) { all_zero = 0; break; }
        }
        g_is64 = all_zero;
    }
}

// ---------------- tiny prep: composed edge matrices -> w_l, d_l ----------------
__global__ void prep_kernel(const float* We1, const float* be1, const float* att1,
                            const float* We2, const float* be2, const float* att2,
                            const float* We3, const float* be3, const float* att3) {
    __shared__ float M2[64], M3[64], c1[8], c2[8], c3[8];
    int t = threadIdx.x;            // 64 threads
    int i = t >> 3, j = t & 7;
    float acc = 0.f;
    for (int k = 0; k < 8; k++) acc += We1[i * 8 + k] * We2[k * 8 + j];
    M2[t] = acc;
    if (i == 0) {
        float c = be2[j];
        for (int k = 0; k < 8; k++) c += be1[k] * We2[k * 8 + j];
        c2[j] = c;
        c1[j] = be1[j];
    }
    __syncthreads();
    float acc3 = 0.f;
    for (int k = 0; k < 8; k++) acc3 += M2[i * 8 + k] * We3[k * 8 + j];
    M3[t] = acc3;
    if (i == 0) {
        float c = be3[j];
        for (int k = 0; k < 8; k++) c += c2[k] * We3[k * 8 + j];
        c3[j] = c;
    }
    __syncthreads();
    if (t < 24) {
        int l = t >> 3, k = t & 7;
        const float* ae = (l == 0 ? att1 : (l == 1 ? att2 : att3)) + 64;
        float w = 0.f;
        for (int jj = 0; jj < 8; jj++) {
            float m = (l == 0) ? We1[k * 8 + jj] : (l == 1 ? M2[k * 8 + jj] : M3[k * 8 + jj]);
            w += m * ae[jj];
        }
        g_w[l][k] = w;
    }
    if (t < 3) {
        const float* ae = (t == 0 ? att1 : (t == 1 ? att2 : att3)) + 64;
        const float* c = (t == 0 ? c1 : (t == 1 ? c2 : c3));
        float d = 0.f;
        for (int jj = 0; jj < 8; jj++) d += c[jj] * ae[jj];
        g_d[t] = d;
    }
    for (int idx = t; idx < GG * HH; idx += 64) g_pool[idx] = 0.f;
    if (t < GG) g_cnt[t] = 0.f;
}

// ---------------- degree histogram: 4 edges per thread ----------------
__global__ void deg_kernel(const void* __restrict__ eidxv) {
    int t = blockIdx.x * blockDim.x + threadIdx.x;
    if (t * 4 >= EE) return;
    int d[4];
    if (g_is64) {
        const longlong4* p = (const longlong4*)((const long long*)eidxv + EE);
        longlong4 q = p[t];
        d[0] = (int)q.x; d[1] = (int)q.y; d[2] = (int)q.z; d[3] = (int)q.w;
    } else {
        const int4* p = (const int4*)((const int*)eidxv + EE);
        int4 q = p[t];
        d[0] = q.x; d[1] = q.y; d[2] = q.z; d[3] = q.w;
    }
#pragma unroll
    for (int i = 0; i < 4; i++) {
        int dn = min(max(d[i], 0), NN - 1);
        atomicAdd(&g_deg[dn], 1);
    }
}

// ---------------- multi-block scan ----------------
__global__ void scanA_kernel() {
    __shared__ int sh[32];
    int i = blockIdx.x * 1024 + threadIdx.x;
    int v = (i < NN) ? g_deg[i] : 0;
#pragma unroll
    for (int off = 16; off > 0; off >>= 1) v += __shfl_down_sync(0xffffffffu, v, off);
    if ((threadIdx.x & 31) == 0) sh[threadIdx.x >> 5] = v;
    __syncthreads();
    if (threadIdx.x < 32) {
        int x = sh[threadIdx.x];
#pragma unroll
        for (int off = 16; off > 0; off >>= 1) x += __shfl_down_sync(0xffffffffu, x, off);
        if (threadIdx.x == 0) g_bsum[blockIdx.x] = x;
    }
}
__global__ void scanB_kernel() {
    __shared__ int sh[64];
    int t = threadIdx.x;
    int v = (t < NB) ? g_bsum[t] : 0;
    sh[t] = v;
    __syncthreads();
    for (int off = 1; off < 64; off <<= 1) {
        int x = (t >= off) ? sh[t - off] : 0;
        __syncthreads();
        sh[t] += x;
        __syncthreads();
    }
    if (t < NB) g_boff[t] = sh[t] - v;   // exclusive
}
__global__ void scanC_kernel() {
    __shared__ int wsum[32];
    int tid = threadIdx.x;
    int lane = tid & 31, wid = tid >> 5;
    int i = blockIdx.x * 1024 + tid;
    int v = (i < NN) ? g_deg[i] : 0;
    // warp inclusive scan
    int incl = v;
#pragma unroll
    for (int off = 1; off < 32; off <<= 1) {
        int x = __shfl_up_sync(0xffffffffu, incl, off);
        if (lane >= off) incl += x;
    }
    if (lane == 31) wsum[wid] = incl;
    __syncthreads();
    if (wid == 0) {
        int x = wsum[lane];
        int xi = x;
#pragma unroll
        for (int off = 1; off < 32; off <<= 1) {
            int y = __shfl_up_sync(0xffffffffu, xi, off);
            if (lane >= off) xi += y;
        }
        wsum[lane] = xi - x;   // exclusive warp offsets
    }
    __syncthreads();
    int excl = incl - v + wsum[wid] + g_boff[blockIdx.x];
    if (i < NN) { g_rowptr[i] = excl; g_cursor[i] = excl; }
    if (i == 0) g_rowptr[NN] = EE;
}

// ---------------- fused eterm + scatter: 4 edges per thread, phase-split ----------------
__global__ void scatter_fused_kernel(const void* __restrict__ eidxv,
                                     const float* __restrict__ ea) {
    int t = blockIdx.x * blockDim.x + threadIdx.x;
    if (t * 4 >= EE) return;
    int sn[4], dn[4];
    if (g_is64) {
        const longlong4* ps = (const longlong4*)eidxv;
        const longlong4* pd = (const longlong4*)((const long long*)eidxv + EE);
        longlong4 qs = ps[t], qd = pd[t];
        sn[0] = (int)qs.x; sn[1] = (int)qs.y; sn[2] = (int)qs.z; sn[3] = (int)qs.w;
        dn[0] = (int)qd.x; dn[1] = (int)qd.y; dn[2] = (int)qd.z; dn[3] = (int)qd.w;
    } else {
        const int4* ps = (const int4*)eidxv;
        const int4* pd = (const int4*)((const int*)eidxv + EE);
        int4 qs = ps[t], qd = pd[t];
        sn[0] = qs.x; sn[1] = qs.y; sn[2] = qs.z; sn[3] = qs.w;
        dn[0] = qd.x; dn[1] = qd.y; dn[2] = qd.z; dn[3] = qd.w;
    }
    const float4* ea4 = (const float4*)ea;
    float4 pay[4];
#pragma unroll
    for (int k = 0; k < 4; k++) {
        int e = t * 4 + k;
        int s = min(max(sn[k], 0), NN - 1);
        float4 a0 = ea4[e * 2];
        float4 a1 = ea4[e * 2 + 1];
        float et[3];
#pragma unroll
        for (int l = 0; l < 3; l++) {
            const float* w = g_w[l];
            et[l] = g_d[l]
                  + a0.x * w[0] + a0.y * w[1] + a0.z * w[2] + a0.w * w[3]
                  + a1.x * w[4] + a1.y * w[5] + a1.z * w[6] + a1.w * w[7];
        }
        pay[k] = make_float4(__int_as_float(s), et[0], et[1], et[2]);
    }
    int pos[4];
#pragma unroll
    for (int k = 0; k < 4; k++) {
        int d = min(max(dn[k], 0), NN - 1);
        pos[k] = atomicAdd(&g_cursor[d], 1);
    }
#pragma unroll
    for (int k = 0; k < 4; k++) g_csr[pos[k]] = pay[k];
}

// ---------------- node linear: smem-staged input, fp16 xn output ----------------
template <int IN, bool RELU, bool FROM_GOUT>
__global__ void node_linear_kernel(const float* __restrict__ xin_ext,
                                   const float* __restrict__ W,
                                   const float* __restrict__ b,
                                   const float* __restrict__ att) {
    __shared__ float sW[IN * HH];
    __shared__ float sb[HH];
    __shared__ float sA[64];
    __shared__ float sX[256 * (IN + 1)];
    int tid = threadIdx.x;
    for (int i = tid; i < IN * HH; i += blockDim.x) sW[i] = W[i];
    if (tid < HH) sb[tid] = b[tid];
    if (tid < 64) sA[tid] = att[tid];
    int base = blockIdx.x * 256;
    int nvalid = min(256, NN - base);
    const float* src = FROM_GOUT ? g_out : xin_ext;
    for (int i = tid; i < nvalid * IN; i += 256) {
        int nl = i / IN;
        int k = i - nl * IN;
        sX[nl * (IN + 1) + k] = src[(size_t)base * IN + i];
    }
    __syncthreads();
    int node = base + tid;
    if (tid >= nvalid) return;
    const float* xr = sX + tid * (IN + 1);
    float acc[HH];
#pragma unroll
    for (int h = 0; h < HH; h++) acc[h] = sb[h];
#pragma unroll
    for (int k = 0; k < IN; k++) {
        float xv = xr[k];
        if (RELU) xv = fmaxf(xv, 0.f);
#pragma unroll
        for (int h = 0; h < HH; h++) acc[h] = fmaf(xv, sW[k * HH + h], acc[h]);
    }
    // pack to fp16: 32 halves = 4 uint4 stores
    uint4* o = (uint4*)(g_xnh + (size_t)node * 16);
#pragma unroll
    for (int q = 0; q < 4; q++) {
        uint4 pk;
        __half2 h0 = __floats2half2_rn(acc[8 * q + 0], acc[8 * q + 1]);
        __half2 h1 = __floats2half2_rn(acc[8 * q + 2], acc[8 * q + 3]);
        __half2 h2 = __floats2half2_rn(acc[8 * q + 4], acc[8 * q + 5]);
        __half2 h3 = __floats2half2_rn(acc[8 * q + 6], acc[8 * q + 7]);
        pk.x = *(unsigned*)&h0; pk.y = *(unsigned*)&h1;
        pk.z = *(unsigned*)&h2; pk.w = *(unsigned*)&h3;
        o[q] = pk;
    }
    float u = 0.f, v = 0.f;
#pragma unroll
    for (int h = 0; h < HH; h++) {
        u = fmaf(acc[h], sA[h], u);
        v = fmaf(acc[h], sA[h + 32], v);
    }
    g_u[node] = u;
    g_v[node] = v;
}

// ---------------- fused softmax + aggregate: one warp per dst node ----------------
// Phase 1: 32 lanes compute p for 32 edges, stage {sn,p} in smem.
// Phase 2: 8 edges in parallel, 4 lanes each take 8 halves (16B) of the fp16 src row.
template <int L>
__global__ void edge_fused_kernel() {
    __shared__ __align__(8) float2 sE[8][32];
    int wib = threadIdx.x >> 5;
    int w = (blockIdx.x * blockDim.x + threadIdx.x) >> 5;
    int lane = threadIdx.x & 31;
    if (w >= NN) return;
    int start = g_rowptr[w];
    int end = g_rowptr[w + 1];
    float u = g_u[w];
    int part = lane & 3, grp = lane >> 2;
    float acc[8] = {0.f, 0.f, 0.f, 0.f, 0.f, 0.f, 0.f, 0.f};
    float s = 0.f;
    for (int base = start; base < end; base += 32) {
        int e = base + lane;
        float p = 0.f; int sn = 0;
        if (e < end) {
            float4 q = g_csr[e];
            sn = __float_as_int(q.x);
            float et = (L == 0) ? q.y : (L == 1) ? q.z : q.w;
            float lg = u + g_v[sn] + et;
            lg = (lg > 0.f) ? lg : NEG_SLOPE * lg;
            p = __expf(lg);
        }
        sE[wib][lane] = make_float2(__int_as_float(sn), p);
        __syncwarp();
        int cnt = min(32, end - base);
        for (int j = grp; j < cnt; j += 8) {
            float2 sp = sE[wib][j];
            int snn = __float_as_int(sp.x);
            float pp = sp.y;
            const uint4* row = (const uint4*)(g_xnh + (size_t)snn * 16);
            uint4 rv = row[part];
            float2 f0 = __half22float2(*(__half2*)&rv.x);
            float2 f1 = __half22float2(*(__half2*)&rv.y);
            float2 f2 = __half22float2(*(__half2*)&rv.z);
            float2 f3 = __half22float2(*(__half2*)&rv.w);
            acc[0] = fmaf(pp, f0.x, acc[0]);
            acc[1] = fmaf(pp, f0.y, acc[1]);
            acc[2] = fmaf(pp, f1.x, acc[2]);
            acc[3] = fmaf(pp, f1.y, acc[3]);
            acc[4] = fmaf(pp, f2.x, acc[4]);
            acc[5] = fmaf(pp, f2.y, acc[5]);
            acc[6] = fmaf(pp, f3.x, acc[6]);
            acc[7] = fmaf(pp, f3.y, acc[7]);
            s += pp;
        }
        __syncwarp();
    }
    // reduce across the 8 groups (same part, different grp)
#pragma unroll
    for (int off = 16; off >= 4; off >>= 1) {
#pragma unroll
        for (int i = 0; i < 8; i++) acc[i] += __shfl_down_sync(0xffffffffu, acc[i], off);
        s += __shfl_down_sync(0xffffffffu, s, off);
    }
    if (grp == 0) {
        float inv = 1.f / (s + 1e-16f);
        float4* o = (float4*)(g_out + (size_t)w * HH);
        o[part * 2]     = make_float4(acc[0] * inv, acc[1] * inv, acc[2] * inv, acc[3] * inv);
        o[part * 2 + 1] = make_float4(acc[4] * inv, acc[5] * inv, acc[6] * inv, acc[7] * inv);
    }
}

// ---------------- mean pool over sorted batch ----------------
__global__ void pool_kernel(const void* __restrict__ batchv) {
    int w = (blockIdx.x * blockDim.x + threadIdx.x) >> 5;
    int lane = threadIdx.x & 31;
    int base = w * 32;
    if (base >= NN) return;
    int is64 = g_is64;
    int nmax = min(32, NN - base);
    int myb = 0;
    if (lane < nmax) {
        if (is64) myb = (int)((const long long*)batchv)[base + lane];
        else      myb = ((const int*)batchv)[base + lane];
        myb = min(max(myb, 0), GG - 1);
    }
    float acc = 0.f, cnt = 0.f;
    int curb = __shfl_sync(0xffffffffu, myb, 0);
    for (int n = 0; n < nmax; n++) {
        int b = __shfl_sync(0xffffffffu, myb, n);
        if (b != curb) {
            atomicAdd(&g_pool[curb * HH + lane], acc);
            if (lane == 0) atomicAdd(&g_cnt[curb], cnt);
            acc = 0.f; cnt = 0.f; curb = b;
        }
        acc += g_out[(size_t)(base + n) * HH + lane];
        cnt += 1.f;
    }
    atomicAdd(&g_pool[curb * HH + lane], acc);
    if (lane == 0) atomicAdd(&g_cnt[curb], cnt);
}

// ---------------- head ----------------
__global__ void head_kernel(const float* __restrict__ Wlin, const float* __restrict__ blin,
                            float* __restrict__ out) {
    int g = threadIdx.x >> 5;
    int lane = threadIdx.x & 31;
    if (g >= GG) return;
    float v = g_pool[g * HH + lane] * Wlin[lane];
#pragma unroll
    for (int o = 16; o > 0; o >>= 1) v += __shfl_xor_sync(0xffffffffu, v, o);
    if (lane == 0) out[g] = v / fmaxf(g_cnt[g], 1.f) + blin[0];
}

// ---------------- launch ----------------
extern "C" void kernel_launch(void* const* d_in, const int* in_sizes, int n_in,
                              void* d_out, int out_size) {
    const float* x     = (const float*)d_in[0];
    const float* ea    = (const float*)d_in[1];
    const void*  eidx  = d_in[2];
    const void*  batch = d_in[3];
    const float *Wn1 = (const float*)d_in[4],  *bn1 = (const float*)d_in[5];
    const float *We1 = (const float*)d_in[6],  *be1 = (const float*)d_in[7],  *att1 = (const float*)d_in[8];
    const float *Wn2 = (const float*)d_in[9],  *bn2 = (const float*)d_in[10];
    const float *We2 = (const float*)d_in[11], *be2 = (const float*)d_in[12], *att2 = (const float*)d_in[13];
    const float *Wn3 = (const float*)d_in[14], *bn3 = (const float*)d_in[15];
    const float *We3 = (const float*)d_in[16], *be3 = (const float*)d_in[17], *att3 = (const float*)d_in[18];
    const float *Wlin = (const float*)d_in[19], *blin = (const float*)d_in[20];
    float* out = (float*)d_out;

    const int NODE_BLOCKS = (NN + 255) / 256;
    const int WARP_BLOCKS = (NN * 32 + 255) / 256;

    detect_zero_kernel<<<NODE_BLOCKS, 256>>>((const int*)eidx);
    prep_kernel<<<1, 64>>>(We1, be1, att1, We2, be2, att2, We3, be3, att3);
    deg_kernel<<<(EE / 4 + 255) / 256, 256>>>(eidx);
    scanA_kernel<<<NB, 1024>>>();
    scanB_kernel<<<1, 64>>>();
    scanC_kernel<<<NB, 1024>>>();
    scatter_fused_kernel<<<(EE / 4 + 255) / 256, 256>>>(eidx, ea);

    // layer 1
    node_linear_kernel<16, false, false><<<NODE_BLOCKS, 256>>>(x, Wn1, bn1, att1);
    edge_fused_kernel<0><<<WARP_BLOCKS, 256>>>();
    // layer 2
    node_linear_kernel<32, true, true><<<NODE_BLOCKS, 256>>>(nullptr, Wn2, bn2, att2);
    edge_fused_kernel<1><<<WARP_BLOCKS, 256>>>();
    // layer 3
    node_linear_kernel<32, true, true><<<NODE_BLOCKS, 256>>>(nullptr, Wn3, bn3, att3);
    edge_fused_kernel<2><<<WARP_BLOCKS, 256>>>();

    // pooling + head
    pool_kernel<<<NODE_BLOCKS, 256>>>(batch);
    head_kernel<<<1, 512>>>(Wlin, blin, out);
}

// round 10
// speedup vs baseline: 2.1059x; 1.0614x over previous
#include <cuda_runtime.h>
#include <cuda_fp16.h>

#define NN 50000
#define EE 1600000
#define GG 16
#define HH 32
#define NEG_SLOPE 0.2f
#define NB 49   // scan blocks: ceil(50000/1024)

// ---------------- device scratch (static, no allocs) ----------------
__device__ __align__(128) __half2 g_xnh[NN * 16];   // fp16 node feats (gather target)
__device__ __align__(128) float g_out[NN * HH];     // fp32 layer output / next input
__device__ float g_u[NN];
__device__ float g_v[NN];
__device__ __align__(16) float4 g_csr[EE];          // {src_bits, et1, et2, et3} grouped by dst
__device__ int   g_deg[NN];                         // zero-initialized; re-zeroed by pool each call
__device__ int   g_rowptr[NN + 1];
__device__ int   g_cursor[NN];
__device__ int   g_bsum[NB];
__device__ __align__(16) float g_w[3][8];
__device__ float g_d[3];
__device__ float g_pool[GG * HH];
__device__ float g_cnt[GG];

// ---------------- per-block dtype sniff: int64 ids have zero high halves ----------------
__device__ __forceinline__ int block_is64(const int* __restrict__ words) {
    __shared__ int sh_is64;
    if (threadIdx.x == 0) {
        int az = 1;
        for (int i = 0; i < 64; i++) {
            if (words[2 * i + 1] != 0) { az = 0; break; }
        }
        sh_is64 = az;
    }
    __syncthreads();
    return sh_is64;
}

// ---------------- deg histogram (4 edges/thread) + prep (block 0) ----------------
__global__ void deg_prep_kernel(const void* __restrict__ eidxv,
                                const float* We1, const float* be1, const float* att1,
                                const float* We2, const float* be2, const float* att2,
                                const float* We3, const float* be3, const float* att3) {
    int is64 = block_is64((const int*)eidxv);

    if (blockIdx.x == 0) {
        // ---- prep: composed edge matrices -> w_l, d_l; zero pool accumulators ----
        __shared__ float M2[64], M3[64], c1[8], c2[8], c3[8];
        int t = threadIdx.x;
        if (t < 64) {
            int i = t >> 3, j = t & 7;
            float acc = 0.f;
            for (int k = 0; k < 8; k++) acc += We1[i * 8 + k] * We2[k * 8 + j];
            M2[t] = acc;
            if (i == 0) {
                float c = be2[j];
                for (int k = 0; k < 8; k++) c += be1[k] * We2[k * 8 + j];
                c2[j] = c;
                c1[j] = be1[j];
            }
        }
        __syncthreads();
        if (t < 64) {
            int i = t >> 3, j = t & 7;
            float acc3 = 0.f;
            for (int k = 0; k < 8; k++) acc3 += M2[i * 8 + k] * We3[k * 8 + j];
            M3[t] = acc3;
            if (i == 0) {
                float c = be3[j];
                for (int k = 0; k < 8; k++) c += c2[k] * We3[k * 8 + j];
                c3[j] = c;
            }
        }
        __syncthreads();
        if (t < 24) {
            int l = t >> 3, k = t & 7;
            const float* ae = (l == 0 ? att1 : (l == 1 ? att2 : att3)) + 64;
            float w = 0.f;
            for (int jj = 0; jj < 8; jj++) {
                float m = (l == 0) ? We1[k * 8 + jj] : (l == 1 ? M2[k * 8 + jj] : M3[k * 8 + jj]);
                w += m * ae[jj];
            }
            g_w[l][k] = w;
        }
        if (t < 3) {
            const float* ae = (t == 0 ? att1 : (t == 1 ? att2 : att3)) + 64;
            const float* c = (t == 0 ? c1 : (t == 1 ? c2 : c3));
            float d = 0.f;
            for (int jj = 0; jj < 8; jj++) d += c[jj] * ae[jj];
            g_d[t] = d;
        }
        for (int idx = t; idx < GG * HH; idx += blockDim.x) g_pool[idx] = 0.f;
        if (t < GG) g_cnt[t] = 0.f;
    }

    // ---- degree histogram ----
    int t4 = blockIdx.x * blockDim.x + threadIdx.x;
    if (t4 * 4 >= EE) return;
    int d[4];
    if (is64) {
        const longlong4* p = (const longlong4*)((const long long*)eidxv + EE);
        longlong4 q = p[t4];
        d[0] = (int)q.x; d[1] = (int)q.y; d[2] = (int)q.z; d[3] = (int)q.w;
    } else {
        const int4* p = (const int4*)((const int*)eidxv + EE);
        int4 q = p[t4];
        d[0] = q.x; d[1] = q.y; d[2] = q.z; d[3] = q.w;
    }
#pragma unroll
    for (int i = 0; i < 4; i++) {
        int dn = min(max(d[i], 0), NN - 1);
        atomicAdd(&g_deg[dn], 1);
    }
}

// ---------------- scanA: per-1024-chunk sums ----------------
__global__ void scanA_kernel() {
    __shared__ int sh[32];
    int i = blockIdx.x * 1024 + threadIdx.x;
    int v = (i < NN) ? g_deg[i] : 0;
#pragma unroll
    for (int off = 16; off > 0; off >>= 1) v += __shfl_down_sync(0xffffffffu, v, off);
    if ((threadIdx.x & 31) == 0) sh[threadIdx.x >> 5] = v;
    __syncthreads();
    if (threadIdx.x < 32) {
        int x = sh[threadIdx.x];
#pragma unroll
        for (int off = 16; off > 0; off >>= 1) x += __shfl_down_sync(0xffffffffu, x, off);
        if (threadIdx.x == 0) g_bsum[blockIdx.x] = x;
    }
}

// ---------------- scanC: local scan + inline block-offset reduction ----------------
__global__ void scanC_kernel() {
    __shared__ int wsum[32];
    __shared__ int sred[2];
    int tid = threadIdx.x;
    int lane = tid & 31, wid = tid >> 5;
    // block offset = sum of g_bsum[j] for j < blockIdx.x (NB=49 values, 2 warps)
    if (tid < 64) {
        int v = (tid < blockIdx.x && tid < NB) ? g_bsum[tid] : 0;
#pragma unroll
        for (int off = 16; off > 0; off >>= 1) v += __shfl_down_sync(0xffffffffu, v, off);
        if ((tid & 31) == 0) sred[tid >> 5] = v;
    }
    int i = blockIdx.x * 1024 + tid;
    int v = (i < NN) ? g_deg[i] : 0;
    int incl = v;
#pragma unroll
    for (int off = 1; off < 32; off <<= 1) {
        int x = __shfl_up_sync(0xffffffffu, incl, off);
        if (lane >= off) incl += x;
    }
    if (lane == 31) wsum[wid] = incl;
    __syncthreads();
    if (wid == 0) {
        int x = wsum[lane];
        int xi = x;
#pragma unroll
        for (int off = 1; off < 32; off <<= 1) {
            int y = __shfl_up_sync(0xffffffffu, xi, off);
            if (lane >= off) xi += y;
        }
        wsum[lane] = xi - x;
    }
    __syncthreads();
    int excl = incl - v + wsum[wid] + sred[0] + sred[1];
    if (i < NN) { g_rowptr[i] = excl; g_cursor[i] = excl; }
    if (i == 0) g_rowptr[NN] = EE;
}

// ---------------- fused eterm + scatter: 4 edges per thread, phase-split ----------------
__global__ void scatter_fused_kernel(const void* __restrict__ eidxv,
                                     const float* __restrict__ ea) {
    int is64 = block_is64((const int*)eidxv);
    int t = blockIdx.x * blockDim.x + threadIdx.x;
    if (t * 4 >= EE) return;
    int sn[4], dn[4];
    if (is64) {
        const longlong4* ps = (const longlong4*)eidxv;
        const longlong4* pd = (const longlong4*)((const long long*)eidxv + EE);
        longlong4 qs = ps[t], qd = pd[t];
        sn[0] = (int)qs.x; sn[1] = (int)qs.y; sn[2] = (int)qs.z; sn[3] = (int)qs.w;
        dn[0] = (int)qd.x; dn[1] = (int)qd.y; dn[2] = (int)qd.z; dn[3] = (int)qd.w;
    } else {
        const int4* ps = (const int4*)eidxv;
        const int4* pd = (const int4*)((const int*)eidxv + EE);
        int4 qs = ps[t], qd = pd[t];
        sn[0] = qs.x; sn[1] = qs.y; sn[2] = qs.z; sn[3] = qs.w;
        dn[0] = qd.x; dn[1] = qd.y; dn[2] = qd.z; dn[3] = qd.w;
    }
    const float4* ea4 = (const float4*)ea;
    float4 pay[4];
#pragma unroll
    for (int k = 0; k < 4; k++) {
        int e = t * 4 + k;
        int s = min(max(sn[k], 0), NN - 1);
        float4 a0 = ea4[e * 2];
        float4 a1 = ea4[e * 2 + 1];
        float et[3];
#pragma unroll
        for (int l = 0; l < 3; l++) {
            const float* w = g_w[l];
            et[l] = g_d[l]
                  + a0.x * w[0] + a0.y * w[1] + a0.z * w[2] + a0.w * w[3]
                  + a1.x * w[4] + a1.y * w[5] + a1.z * w[6] + a1.w * w[7];
        }
        pay[k] = make_float4(__int_as_float(s), et[0], et[1], et[2]);
    }
    int pos[4];
#pragma unroll
    for (int k = 0; k < 4; k++) {
        int d = min(max(dn[k], 0), NN - 1);
        pos[k] = atomicAdd(&g_cursor[d], 1);
    }
#pragma unroll
    for (int k = 0; k < 4; k++) g_csr[pos[k]] = pay[k];
}

// ---------------- node linear: smem-staged input, fp16 xn output ----------------
template <int IN, bool RELU, bool FROM_GOUT>
__global__ void node_linear_kernel(const float* __restrict__ xin_ext,
                                   const float* __restrict__ W,
                                   const float* __restrict__ b,
                                   const float* __restrict__ att) {
    __shared__ float sW[IN * HH];
    __shared__ float sb[HH];
    __shared__ float sA[64];
    __shared__ float sX[256 * (IN + 1)];
    int tid = threadIdx.x;
    for (int i = tid; i < IN * HH; i += blockDim.x) sW[i] = W[i];
    if (tid < HH) sb[tid] = b[tid];
    if (tid < 64) sA[tid] = att[tid];
    int base = blockIdx.x * 256;
    int nvalid = min(256, NN - base);
    const float* src = FROM_GOUT ? g_out : xin_ext;
    for (int i = tid; i < nvalid * IN; i += 256) {
        int nl = i / IN;
        int k = i - nl * IN;
        sX[nl * (IN + 1) + k] = src[(size_t)base * IN + i];
    }
    __syncthreads();
    int node = base + tid;
    if (tid >= nvalid) return;
    const float* xr = sX + tid * (IN + 1);
    float acc[HH];
#pragma unroll
    for (int h = 0; h < HH; h++) acc[h] = sb[h];
#pragma unroll
    for (int k = 0; k < IN; k++) {
        float xv = xr[k];
        if (RELU) xv = fmaxf(xv, 0.f);
#pragma unroll
        for (int h = 0; h < HH; h++) acc[h] = fmaf(xv, sW[k * HH + h], acc[h]);
    }
    uint4* o = (uint4*)(g_xnh + (size_t)node * 16);
#pragma unroll
    for (int q = 0; q < 4; q++) {
        uint4 pk;
        __half2 h0 = __floats2half2_rn(acc[8 * q + 0], acc[8 * q + 1]);
        __half2 h1 = __floats2half2_rn(acc[8 * q + 2], acc[8 * q + 3]);
        __half2 h2 = __floats2half2_rn(acc[8 * q + 4], acc[8 * q + 5]);
        __half2 h3 = __floats2half2_rn(acc[8 * q + 6], acc[8 * q + 7]);
        pk.x = *(unsigned*)&h0; pk.y = *(unsigned*)&h1;
        pk.z = *(unsigned*)&h2; pk.w = *(unsigned*)&h3;
        o[q] = pk;
    }
    float u = 0.f, v = 0.f;
#pragma unroll
    for (int h = 0; h < HH; h++) {
        u = fmaf(acc[h], sA[h], u);
        v = fmaf(acc[h], sA[h + 32], v);
    }
    g_u[node] = u;
    g_v[node] = v;
}

// ---------------- fused softmax + aggregate: one warp per dst node ----------------
// Phase 1: 32 lanes compute p for 32 edges, stage {sn,p} in smem.
// Phase 2: 8 edges in parallel, 4 lanes each, software-pipelined (1-iter lookahead).
template <int L>
__global__ void edge_fused_kernel() {
    __shared__ __align__(8) float2 sE[8][32];
    int wib = threadIdx.x >> 5;
    int w = (blockIdx.x * blockDim.x + threadIdx.x) >> 5;
    int lane = threadIdx.x & 31;
    if (w >= NN) return;
    int start = g_rowptr[w];
    int end = g_rowptr[w + 1];
    float u = g_u[w];
    int part = lane & 3, grp = lane >> 2;
    float acc[8] = {0.f, 0.f, 0.f, 0.f, 0.f, 0.f, 0.f, 0.f};
    float s = 0.f;
    for (int base = start; base < end; base += 32) {
        int e = base + lane;
        float p = 0.f; int sn = 0;
        if (e < end) {
            float4 q = g_csr[e];
            sn = __float_as_int(q.x);
            float et = (L == 0) ? q.y : (L == 1) ? q.z : q.w;
            float lg = u + g_v[sn] + et;
            lg = (lg > 0.f) ? lg : NEG_SLOPE * lg;
            p = __expf(lg);
        }
        sE[wib][lane] = make_float2(__int_as_float(sn), p);
        __syncwarp();
        int cnt = min(32, end - base);
        // pipelined: prefetch j+8 while consuming j
        int j = grp;
        uint4 rv; float pp = 0.f;
        bool have = j < cnt;
        if (have) {
            float2 sp = sE[wib][j];
            pp = sp.y;
            rv = ((const uint4*)(g_xnh + (size_t)__float_as_int(sp.x) * 16))[part];
        }
        while (have) {
            int jn = j + 8;
            uint4 rvn; float ppn = 0.f;
            bool haven = jn < cnt;
            if (haven) {
                float2 sp = sE[wib][jn];
                ppn = sp.y;
                rvn = ((const uint4*)(g_xnh + (size_t)__float_as_int(sp.x) * 16))[part];
            }
            float2 f0 = __half22float2(*(__half2*)&rv.x);
            float2 f1 = __half22float2(*(__half2*)&rv.y);
            float2 f2 = __half22float2(*(__half2*)&rv.z);
            float2 f3 = __half22float2(*(__half2*)&rv.w);
            acc[0] = fmaf(pp, f0.x, acc[0]);
            acc[1] = fmaf(pp, f0.y, acc[1]);
            acc[2] = fmaf(pp, f1.x, acc[2]);
            acc[3] = fmaf(pp, f1.y, acc[3]);
            acc[4] = fmaf(pp, f2.x, acc[4]);
            acc[5] = fmaf(pp, f2.y, acc[5]);
            acc[6] = fmaf(pp, f3.x, acc[6]);
            acc[7] = fmaf(pp, f3.y, acc[7]);
            s += pp;
            rv = rvn; pp = ppn; j = jn; have = haven;
        }
        __syncwarp();
    }
#pragma unroll
    for (int off = 16; off >= 4; off >>= 1) {
#pragma unroll
        for (int i = 0; i < 8; i++) acc[i] += __shfl_down_sync(0xffffffffu, acc[i], off);
        s += __shfl_down_sync(0xffffffffu, s, off);
    }
    if (grp == 0) {
        float inv = 1.f / (s + 1e-16f);
        float4* o = (float4*)(g_out + (size_t)w * HH);
        o[part * 2]     = make_float4(acc[0] * inv, acc[1] * inv, acc[2] * inv, acc[3] * inv);
        o[part * 2 + 1] = make_float4(acc[4] * inv, acc[5] * inv, acc[6] * inv, acc[7] * inv);
    }
}

// ---------------- mean pool over sorted batch; re-zero g_deg for next call ----------------
__global__ void pool_kernel(const void* __restrict__ batchv, const int* __restrict__ eidx_words) {
    int is64 = block_is64(eidx_words);
    int gtid = blockIdx.x * blockDim.x + threadIdx.x;
    if (gtid < NN) g_deg[gtid] = 0;          // reset histogram for next launch
    int w = gtid >> 5;
    int lane = threadIdx.x & 31;
    int base = w * 32;
    if (base >= NN) return;
    int nmax = min(32, NN - base);
    int myb = 0;
    if (lane < nmax) {
        if (is64) myb = (int)((const long long*)batchv)[base + lane];
        else      myb = ((const int*)batchv)[base + lane];
        myb = min(max(myb, 0), GG - 1);
    }
    float acc = 0.f, cnt = 0.f;
    int curb = __shfl_sync(0xffffffffu, myb, 0);
    for (int n = 0; n < nmax; n++) {
        int b = __shfl_sync(0xffffffffu, myb, n);
        if (b != curb) {
            atomicAdd(&g_pool[curb * HH + lane], acc);
            if (lane == 0) atomicAdd(&g_cnt[curb], cnt);
            acc = 0.f; cnt = 0.f; curb = b;
        }
        acc += g_out[(size_t)(base + n) * HH + lane];
        cnt += 1.f;
    }
    atomicAdd(&g_pool[curb * HH + lane], acc);
    if (lane == 0) atomicAdd(&g_cnt[curb], cnt);
}

// ---------------- head ----------------
__global__ void head_kernel(const float* __restrict__ Wlin, const float* __restrict__ blin,
                            float* __restrict__ out) {
    int g = threadIdx.x >> 5;
    int lane = threadIdx.x & 31;
    if (g >= GG) return;
    float v = g_pool[g * HH + lane] * Wlin[lane];
#pragma unroll
    for (int o = 16; o > 0; o >>= 1) v += __shfl_xor_sync(0xffffffffu, v, o);
    if (lane == 0) out[g] = v / fmaxf(g_cnt[g], 1.f) + blin[0];
}

// ---------------- launch ----------------
extern "C" void kernel_launch(void* const* d_in, const int* in_sizes, int n_in,
                              void* d_out, int out_size) {
    const float* x     = (const float*)d_in[0];
    const float* ea    = (const float*)d_in[1];
    const void*  eidx  = d_in[2];
    const void*  batch = d_in[3];
    const float *Wn1 = (const float*)d_in[4],  *bn1 = (const float*)d_in[5];
    const float *We1 = (const float*)d_in[6],  *be1 = (const float*)d_in[7],  *att1 = (const float*)d_in[8];
    const float *Wn2 = (const float*)d_in[9],  *bn2 = (const float*)d_in[10];
    const float *We2 = (const float*)d_in[11], *be2 = (const float*)d_in[12], *att2 = (const float*)d_in[13];
    const float *Wn3 = (const float*)d_in[14], *bn3 = (const float*)d_in[15];
    const float *We3 = (const float*)d_in[16], *be3 = (const float*)d_in[17], *att3 = (const float*)d_in[18];
    const float *Wlin = (const float*)d_in[19], *blin = (const float*)d_in[20];
    float* out = (float*)d_out;

    const int NODE_BLOCKS = (NN + 255) / 256;
    const int WARP_BLOCKS = (NN * 32 + 255) / 256;

    deg_prep_kernel<<<(EE / 4 + 255) / 256, 256>>>(eidx,
        We1, be1, att1, We2, be2, att2, We3, be3, att3);
    scanA_kernel<<<NB, 1024>>>();
    scanC_kernel<<<NB, 1024>>>();
    scatter_fused_kernel<<<(EE / 4 + 255) / 256, 256>>>(eidx, ea);

    // layer 1
    node_linear_kernel<16, false, false><<<NODE_BLOCKS, 256>>>(x, Wn1, bn1, att1);
    edge_fused_kernel<0><<<WARP_BLOCKS, 256>>>();
    // layer 2
    node_linear_kernel<32, true, true><<<NODE_BLOCKS, 256>>>(nullptr, Wn2, bn2, att2);
    edge_fused_kernel<1><<<WARP_BLOCKS, 256>>>();
    // layer 3
    node_linear_kernel<32, true, true><<<NODE_BLOCKS, 256>>>(nullptr, Wn3, bn3, att3);
    edge_fused_kernel<2><<<WARP_BLOCKS, 256>>>();

    // pooling + head
    pool_kernel<<<NODE_BLOCKS, 256>>>(batch, (const int*)eidx);
    head_kernel<<<1, 512>>>(Wlin, blin, out);
}

// round 11
// speedup vs baseline: 2.1747x; 1.0326x over previous
#include <cuda_runtime.h>
#include <cuda_fp16.h>

#define NN 50000
#define EE 1600000
#define GG 16
#define HH 32
#define NEG_SLOPE 0.2f
#define NB 49   // scan blocks: ceil(50000/1024)

// ---------------- device scratch (static, no allocs) ----------------
__device__ __align__(128) __half2 g_xnh[NN * 16];   // fp16 node feats (gather target)
__device__ __align__(128) float g_out[NN * HH];     // fp32 layer output / next input
__device__ float g_u[NN];
__device__ float g_v[NN];
__device__ __align__(16) uint2 g_csr[EE];           // {src|et0h<<16, et1h|et2h<<16} grouped by dst
__device__ int   g_deg[NN];                         // zero-initialized; re-zeroed by pool each call
__device__ int   g_rowptr[NN + 1];
__device__ int   g_cursor[NN];
__device__ int   g_bsum[NB];
__device__ __align__(16) float g_w[3][8];
__device__ float g_d[3];
__device__ float g_pool[GG * HH];
__device__ float g_cnt[GG];

// ---------------- per-block dtype sniff: int64 ids have zero high halves ----------------
__device__ __forceinline__ int block_is64(const int* __restrict__ words) {
    __shared__ int sh_is64;
    if (threadIdx.x == 0) {
        int az = 1;
        for (int i = 0; i < 64; i++) {
            if (words[2 * i + 1] != 0) { az = 0; break; }
        }
        sh_is64 = az;
    }
    __syncthreads();
    return sh_is64;
}

// ---------------- deg histogram (4 edges/thread) + prep (block 0) ----------------
__global__ void deg_prep_kernel(const void* __restrict__ eidxv,
                                const float* We1, const float* be1, const float* att1,
                                const float* We2, const float* be2, const float* att2,
                                const float* We3, const float* be3, const float* att3) {
    int is64 = block_is64((const int*)eidxv);

    if (blockIdx.x == 0) {
        __shared__ float M2[64], M3[64], c1[8], c2[8], c3[8];
        int t = threadIdx.x;
        if (t < 64) {
            int i = t >> 3, j = t & 7;
            float acc = 0.f;
            for (int k = 0; k < 8; k++) acc += We1[i * 8 + k] * We2[k * 8 + j];
            M2[t] = acc;
            if (i == 0) {
                float c = be2[j];
                for (int k = 0; k < 8; k++) c += be1[k] * We2[k * 8 + j];
                c2[j] = c;
                c1[j] = be1[j];
            }
        }
        __syncthreads();
        if (t < 64) {
            int i = t >> 3, j = t & 7;
            float acc3 = 0.f;
            for (int k = 0; k < 8; k++) acc3 += M2[i * 8 + k] * We3[k * 8 + j];
            M3[t] = acc3;
            if (i == 0) {
                float c = be3[j];
                for (int k = 0; k < 8; k++) c += c2[k] * We3[k * 8 + j];
                c3[j] = c;
            }
        }
        __syncthreads();
        if (t < 24) {
            int l = t >> 3, k = t & 7;
            const float* ae = (l == 0 ? att1 : (l == 1 ? att2 : att3)) + 64;
            float w = 0.f;
            for (int jj = 0; jj < 8; jj++) {
                float m = (l == 0) ? We1[k * 8 + jj] : (l == 1 ? M2[k * 8 + jj] : M3[k * 8 + jj]);
                w += m * ae[jj];
            }
            g_w[l][k] = w;
        }
        if (t < 3) {
            const float* ae = (t == 0 ? att1 : (t == 1 ? att2 : att3)) + 64;
            const float* c = (t == 0 ? c1 : (t == 1 ? c2 : c3));
            float d = 0.f;
            for (int jj = 0; jj < 8; jj++) d += c[jj] * ae[jj];
            g_d[t] = d;
        }
        for (int idx = t; idx < GG * HH; idx += blockDim.x) g_pool[idx] = 0.f;
        if (t < GG) g_cnt[t] = 0.f;
    }

    int t4 = blockIdx.x * blockDim.x + threadIdx.x;
    if (t4 * 4 >= EE) return;
    int d[4];
    if (is64) {
        const longlong4* p = (const longlong4*)((const long long*)eidxv + EE);
        longlong4 q = p[t4];
        d[0] = (int)q.x; d[1] = (int)q.y; d[2] = (int)q.z; d[3] = (int)q.w;
    } else {
        const int4* p = (const int4*)((const int*)eidxv + EE);
        int4 q = p[t4];
        d[0] = q.x; d[1] = q.y; d[2] = q.z; d[3] = q.w;
    }
#pragma unroll
    for (int i = 0; i < 4; i++) {
        int dn = min(max(d[i], 0), NN - 1);
        atomicAdd(&g_deg[dn], 1);
    }
}

// ---------------- scanA: per-1024-chunk sums ----------------
__global__ void scanA_kernel() {
    __shared__ int sh[32];
    int i = blockIdx.x * 1024 + threadIdx.x;
    int v = (i < NN) ? g_deg[i] : 0;
#pragma unroll
    for (int off = 16; off > 0; off >>= 1) v += __shfl_down_sync(0xffffffffu, v, off);
    if ((threadIdx.x & 31) == 0) sh[threadIdx.x >> 5] = v;
    __syncthreads();
    if (threadIdx.x < 32) {
        int x = sh[threadIdx.x];
#pragma unroll
        for (int off = 16; off > 0; off >>= 1) x += __shfl_down_sync(0xffffffffu, x, off);
        if (threadIdx.x == 0) g_bsum[blockIdx.x] = x;
    }
}

// ---------------- scanC: local scan + inline block-offset reduction ----------------
__global__ void scanC_kernel() {
    __shared__ int wsum[32];
    __shared__ int sred[2];
    int tid = threadIdx.x;
    int lane = tid & 31, wid = tid >> 5;
    if (tid < 64) {
        int v = (tid < blockIdx.x && tid < NB) ? g_bsum[tid] : 0;
#pragma unroll
        for (int off = 16; off > 0; off >>= 1) v += __shfl_down_sync(0xffffffffu, v, off);
        if ((tid & 31) == 0) sred[tid >> 5] = v;
    }
    int i = blockIdx.x * 1024 + tid;
    int v = (i < NN) ? g_deg[i] : 0;
    int incl = v;
#pragma unroll
    for (int off = 1; off < 32; off <<= 1) {
        int x = __shfl_up_sync(0xffffffffu, incl, off);
        if (lane >= off) incl += x;
    }
    if (lane == 31) wsum[wid] = incl;
    __syncthreads();
    if (wid == 0) {
        int x = wsum[lane];
        int xi = x;
#pragma unroll
        for (int off = 1; off < 32; off <<= 1) {
            int y = __shfl_up_sync(0xffffffffu, xi, off);
            if (lane >= off) xi += y;
        }
        wsum[lane] = xi - x;
    }
    __syncthreads();
    int excl = incl - v + wsum[wid] + sred[0] + sred[1];
    if (i < NN) { g_rowptr[i] = excl; g_cursor[i] = excl; }
    if (i == 0) g_rowptr[NN] = EE;
}

// ---------------- fused eterm + scatter: 4 edges/thread, 8B packed payload ----------------
__global__ void scatter_fused_kernel(const void* __restrict__ eidxv,
                                     const float* __restrict__ ea) {
    int is64 = block_is64((const int*)eidxv);
    int t = blockIdx.x * blockDim.x + threadIdx.x;
    if (t * 4 >= EE) return;
    int sn[4], dn[4];
    if (is64) {
        const longlong4* ps = (const longlong4*)eidxv;
        const longlong4* pd = (const longlong4*)((const long long*)eidxv + EE);
        longlong4 qs = ps[t], qd = pd[t];
        sn[0] = (int)qs.x; sn[1] = (int)qs.y; sn[2] = (int)qs.z; sn[3] = (int)qs.w;
        dn[0] = (int)qd.x; dn[1] = (int)qd.y; dn[2] = (int)qd.z; dn[3] = (int)qd.w;
    } else {
        const int4* ps = (const int4*)eidxv;
        const int4* pd = (const int4*)((const int*)eidxv + EE);
        int4 qs = ps[t], qd = pd[t];
        sn[0] = qs.x; sn[1] = qs.y; sn[2] = qs.z; sn[3] = qs.w;
        dn[0] = qd.x; dn[1] = qd.y; dn[2] = qd.z; dn[3] = qd.w;
    }
    const float4* ea4 = (const float4*)ea;
    uint2 pay[4];
#pragma unroll
    for (int k = 0; k < 4; k++) {
        int e = t * 4 + k;
        unsigned s = (unsigned)min(max(sn[k], 0), NN - 1);
        float4 a0 = ea4[e * 2];
        float4 a1 = ea4[e * 2 + 1];
        float et[3];
#pragma unroll
        for (int l = 0; l < 3; l++) {
            const float* w = g_w[l];
            et[l] = g_d[l]
                  + a0.x * w[0] + a0.y * w[1] + a0.z * w[2] + a0.w * w[3]
                  + a1.x * w[4] + a1.y * w[5] + a1.z * w[6] + a1.w * w[7];
        }
        unsigned h0 = (unsigned)__half_as_ushort(__float2half_rn(et[0]));
        unsigned h1 = (unsigned)__half_as_ushort(__float2half_rn(et[1]));
        unsigned h2 = (unsigned)__half_as_ushort(__float2half_rn(et[2]));
        pay[k].x = s | (h0 << 16);
        pay[k].y = h1 | (h2 << 16);
    }
    int pos[4];
#pragma unroll
    for (int k = 0; k < 4; k++) {
        int d = min(max(dn[k], 0), NN - 1);
        pos[k] = atomicAdd(&g_cursor[d], 1);
    }
#pragma unroll
    for (int k = 0; k < 4; k++) g_csr[pos[k]] = pay[k];
}

// ---------------- node linear: smem-staged input, fp16 xn output ----------------
template <int IN, bool RELU, bool FROM_GOUT>
__global__ void node_linear_kernel(const float* __restrict__ xin_ext,
                                   const float* __restrict__ W,
                                   const float* __restrict__ b,
                                   const float* __restrict__ att) {
    __shared__ float sW[IN * HH];
    __shared__ float sb[HH];
    __shared__ float sA[64];
    __shared__ float sX[256 * (IN + 1)];
    int tid = threadIdx.x;
    for (int i = tid; i < IN * HH; i += blockDim.x) sW[i] = W[i];
    if (tid < HH) sb[tid] = b[tid];
    if (tid < 64) sA[tid] = att[tid];
    int base = blockIdx.x * 256;
    int nvalid = min(256, NN - base);
    const float* src = FROM_GOUT ? g_out : xin_ext;
    for (int i = tid; i < nvalid * IN; i += 256) {
        int nl = i / IN;
        int k = i - nl * IN;
        sX[nl * (IN + 1) + k] = src[(size_t)base * IN + i];
    }
    __syncthreads();
    int node = base + tid;
    if (tid >= nvalid) return;
    const float* xr = sX + tid * (IN + 1);
    float acc[HH];
#pragma unroll
    for (int h = 0; h < HH; h++) acc[h] = sb[h];
#pragma unroll
    for (int k = 0; k < IN; k++) {
        float xv = xr[k];
        if (RELU) xv = fmaxf(xv, 0.f);
#pragma unroll
        for (int h = 0; h < HH; h++) acc[h] = fmaf(xv, sW[k * HH + h], acc[h]);
    }
    uint4* o = (uint4*)(g_xnh + (size_t)node * 16);
#pragma unroll
    for (int q = 0; q < 4; q++) {
        uint4 pk;
        __half2 h0 = __floats2half2_rn(acc[8 * q + 0], acc[8 * q + 1]);
        __half2 h1 = __floats2half2_rn(acc[8 * q + 2], acc[8 * q + 3]);
        __half2 h2 = __floats2half2_rn(acc[8 * q + 4], acc[8 * q + 5]);
        __half2 h3 = __floats2half2_rn(acc[8 * q + 6], acc[8 * q + 7]);
        pk.x = *(unsigned*)&h0; pk.y = *(unsigned*)&h1;
        pk.z = *(unsigned*)&h2; pk.w = *(unsigned*)&h3;
        o[q] = pk;
    }
    float u = 0.f, v = 0.f;
#pragma unroll
    for (int h = 0; h < HH; h++) {
        u = fmaf(acc[h], sA[h], u);
        v = fmaf(acc[h], sA[h + 32], v);
    }
    g_u[node] = u;
    g_v[node] = v;
}

// ---------------- fused softmax + aggregate: one warp per dst node ----------------
template <int L>
__global__ void edge_fused_kernel() {
    __shared__ __align__(8) float2 sE[8][32];
    int wib = threadIdx.x >> 5;
    int w = (blockIdx.x * blockDim.x + threadIdx.x) >> 5;
    int lane = threadIdx.x & 31;
    if (w >= NN) return;
    int start = g_rowptr[w];
    int end = g_rowptr[w + 1];
    float u = g_u[w];
    int part = lane & 3, grp = lane >> 2;
    float acc[8] = {0.f, 0.f, 0.f, 0.f, 0.f, 0.f, 0.f, 0.f};
    float s = 0.f;
    for (int base = start; base < end; base += 32) {
        int e = base + lane;
        float p = 0.f; int sn = 0;
        if (e < end) {
            uint2 q = g_csr[e];
            sn = (int)(q.x & 0xffffu);
            unsigned hb = (L == 0) ? (q.x >> 16) : (L == 1) ? (q.y & 0xffffu) : (q.y >> 16);
            float et = __half2float(__ushort_as_half((unsigned short)hb));
            float lg = u + g_v[sn] + et;
            lg = (lg > 0.f) ? lg : NEG_SLOPE * lg;
            p = __expf(lg);
        }
        sE[wib][lane] = make_float2(__int_as_float(sn), p);
        __syncwarp();
        int cnt = min(32, end - base);
        // pipelined: prefetch j+8 while consuming j
        int j = grp;
        uint4 rv; float pp = 0.f;
        bool have = j < cnt;
        if (have) {
            float2 sp = sE[wib][j];
            pp = sp.y;
            rv = ((const uint4*)(g_xnh + (size_t)__float_as_int(sp.x) * 16))[part];
        }
        while (have) {
            int jn = j + 8;
            uint4 rvn; float ppn = 0.f;
            bool haven = jn < cnt;
            if (haven) {
                float2 sp = sE[wib][jn];
                ppn = sp.y;
                rvn = ((const uint4*)(g_xnh + (size_t)__float_as_int(sp.x) * 16))[part];
            }
            float2 f0 = __half22float2(*(__half2*)&rv.x);
            float2 f1 = __half22float2(*(__half2*)&rv.y);
            float2 f2 = __half22float2(*(__half2*)&rv.z);
            float2 f3 = __half22float2(*(__half2*)&rv.w);
            acc[0] = fmaf(pp, f0.x, acc[0]);
            acc[1] = fmaf(pp, f0.y, acc[1]);
            acc[2] = fmaf(pp, f1.x, acc[2]);
            acc[3] = fmaf(pp, f1.y, acc[3]);
            acc[4] = fmaf(pp, f2.x, acc[4]);
            acc[5] = fmaf(pp, f2.y, acc[5]);
            acc[6] = fmaf(pp, f3.x, acc[6]);
            acc[7] = fmaf(pp, f3.y, acc[7]);
            s += pp;
            rv = rvn; pp = ppn; j = jn; have = haven;
        }
        __syncwarp();
    }
#pragma unroll
    for (int off = 16; off >= 4; off >>= 1) {
#pragma unroll
        for (int i = 0; i < 8; i++) acc[i] += __shfl_down_sync(0xffffffffu, acc[i], off);
        s += __shfl_down_sync(0xffffffffu, s, off);
    }
    if (grp == 0) {
        float inv = 1.f / (s + 1e-16f);
        float4* o = (float4*)(g_out + (size_t)w * HH);
        o[part * 2]     = make_float4(acc[0] * inv, acc[1] * inv, acc[2] * inv, acc[3] * inv);
        o[part * 2 + 1] = make_float4(acc[4] * inv, acc[5] * inv, acc[6] * inv, acc[7] * inv);
    }
}

// ---------------- mean pool over sorted batch; re-zero g_deg for next call ----------------
__global__ void pool_kernel(const void* __restrict__ batchv, const int* __restrict__ eidx_words) {
    int is64 = block_is64(eidx_words);
    int gtid = blockIdx.x * blockDim.x + threadIdx.x;
    if (gtid < NN) g_deg[gtid] = 0;
    int w = gtid >> 5;
    int lane = threadIdx.x & 31;
    int base = w * 32;
    if (base >= NN) return;
    int nmax = min(32, NN - base);
    int myb = 0;
    if (lane < nmax) {
        if (is64) myb = (int)((const long long*)batchv)[base + lane];
        else      myb = ((const int*)batchv)[base + lane];
        myb = min(max(myb, 0), GG - 1);
    }
    float acc = 0.f, cnt = 0.f;
    int curb = __shfl_sync(0xffffffffu, myb, 0);
    for (int n = 0; n < nmax; n++) {
        int b = __shfl_sync(0xffffffffu, myb, n);
        if (b != curb) {
            atomicAdd(&g_pool[curb * HH + lane], acc);
            if (lane == 0) atomicAdd(&g_cnt[curb], cnt);
            acc = 0.f; cnt = 0.f; curb = b;
        }
        acc += g_out[(size_t)(base + n) * HH + lane];
        cnt += 1.f;
    }
    atomicAdd(&g_pool[curb * HH + lane], acc);
    if (lane == 0) atomicAdd(&g_cnt[curb], cnt);
}

// ---------------- head ----------------
__global__ void head_kernel(const float* __restrict__ Wlin, const float* __restrict__ blin,
                            float* __restrict__ out) {
    int g = threadIdx.x >> 5;
    int lane = threadIdx.x & 31;
    if (g >= GG) return;
    float v = g_pool[g * HH + lane] * Wlin[lane];
#pragma unroll
    for (int o = 16; o > 0; o >>= 1) v += __shfl_xor_sync(0xffffffffu, v, o);
    if (lane == 0) out[g] = v / fmaxf(g_cnt[g], 1.f) + blin[0];
}

// ---------------- launch ----------------
extern "C" void kernel_launch(void* const* d_in, const int* in_sizes, int n_in,
                              void* d_out, int out_size) {
    const float* x     = (const float*)d_in[0];
    const float* ea    = (const float*)d_in[1];
    const void*  eidx  = d_in[2];
    const void*  batch = d_in[3];
    const float *Wn1 = (const float*)d_in[4],  *bn1 = (const float*)d_in[5];
    const float *We1 = (const float*)d_in[6],  *be1 = (const float*)d_in[7],  *att1 = (const float*)d_in[8];
    const float *Wn2 = (const float*)d_in[9],  *bn2 = (const float*)d_in[10];
    const float *We2 = (const float*)d_in[11], *be2 = (const float*)d_in[12], *att2 = (const float*)d_in[13];
    const float *Wn3 = (const float*)d_in[14], *bn3 = (const float*)d_in[15];
    const float *We3 = (const float*)d_in[16], *be3 = (const float*)d_in[17], *att3 = (const float*)d_in[18];
    const float *Wlin = (const float*)d_in[19], *blin = (const float*)d_in[20];
    float* out = (float*)d_out;

    const int NODE_BLOCKS = (NN + 255) / 256;
    const int WARP_BLOCKS = (NN * 32 + 255) / 256;

    deg_prep_kernel<<<(EE / 4 + 255) / 256, 256>>>(eidx,
        We1, be1, att1, We2, be2, att2, We3, be3, att3);
    scanA_kernel<<<NB, 1024>>>();
    scanC_kernel<<<NB, 1024>>>();
    scatter_fused_kernel<<<(EE / 4 + 255) / 256, 256>>>(eidx, ea);

    // layer 1
    node_linear_kernel<16, false, false><<<NODE_BLOCKS, 256>>>(x, Wn1, bn1, att1);
    edge_fused_kernel<0><<<WARP_BLOCKS, 256>>>();
    // layer 2
    node_linear_kernel<32, true, true><<<NODE_BLOCKS, 256>>>(nullptr, Wn2, bn2, att2);
    edge_fused_kernel<1><<<WARP_BLOCKS, 256>>>();
    // layer 3
    node_linear_kernel<32, true, true><<<NODE_BLOCKS, 256>>>(nullptr, Wn3, bn3, att3);
    edge_fused_kernel<2><<<WARP_BLOCKS, 256>>>();

    // pooling + head
    pool_kernel<<<NODE_BLOCKS, 256>>>(batch, (const int*)eidx);
    head_kernel<<<1, 512>>>(Wlin, blin, out);
}

// round 12
// speedup vs baseline: 2.3998x; 1.1035x over previous
#include <cuda_runtime.h>
#include <cuda_fp16.h>

#define NN 50000
#define EE 1600000
#define GG 16
#define HH 32
#define NEG_SLOPE 0.2f
#define NB 49   // scan blocks: ceil(50000/1024)

// ---------------- device scratch (static, no allocs) ----------------
__device__ __align__(128) __half2 g_xnh[NN * 16];   // fp16 node feats (gather target)
__device__ __align__(128) float g_out[NN * HH];     // fp32 layer output / next input
__device__ float g_u[NN];
__device__ float g_v[NN];
__device__ __align__(16) uint2 g_csr[EE];           // {src|et0h<<16, et1h|et2h<<16} grouped by dst
__device__ int   g_deg[NN];                         // zero-initialized; re-zeroed by pool each call
__device__ int   g_rowptr[NN + 1];
__device__ int   g_cursor[NN];
__device__ int   g_bsum[NB];
__device__ __align__(16) float g_w[3][8];
__device__ float g_d[3];
__device__ float g_pool[GG * HH];
__device__ float g_cnt[GG];

// ---------------- per-block dtype sniff: int64 ids have zero high halves ----------------
__device__ __forceinline__ int block_is64(const int* __restrict__ words) {
    __shared__ int sh_is64;
    if (threadIdx.x == 0) {
        int az = 1;
        for (int i = 0; i < 64; i++) {
            if (words[2 * i + 1] != 0) { az = 0; break; }
        }
        sh_is64 = az;
    }
    __syncthreads();
    return sh_is64;
}

// ---------------- deg histogram (4 edges/thread) + prep (block 0) ----------------
__global__ void __launch_bounds__(256, 6)
deg_prep_kernel(const void* __restrict__ eidxv,
                const float* We1, const float* be1, const float* att1,
                const float* We2, const float* be2, const float* att2,
                const float* We3, const float* be3, const float* att3) {
    int is64 = block_is64((const int*)eidxv);

    if (blockIdx.x == 0) {
        __shared__ float M2[64], M3[64], c1[8], c2[8], c3[8];
        int t = threadIdx.x;
        if (t < 64) {
            int i = t >> 3, j = t & 7;
            float acc = 0.f;
            for (int k = 0; k < 8; k++) acc += We1[i * 8 + k] * We2[k * 8 + j];
            M2[t] = acc;
            if (i == 0) {
                float c = be2[j];
                for (int k = 0; k < 8; k++) c += be1[k] * We2[k * 8 + j];
                c2[j] = c;
                c1[j] = be1[j];
            }
        }
        __syncthreads();
        if (t < 64) {
            int i = t >> 3, j = t & 7;
            float acc3 = 0.f;
            for (int k = 0; k < 8; k++) acc3 += M2[i * 8 + k] * We3[k * 8 + j];
            M3[t] = acc3;
            if (i == 0) {
                float c = be3[j];
                for (int k = 0; k < 8; k++) c += c2[k] * We3[k * 8 + j];
                c3[j] = c;
            }
        }
        __syncthreads();
        if (t < 24) {
            int l = t >> 3, k = t & 7;
            const float* ae = (l == 0 ? att1 : (l == 1 ? att2 : att3)) + 64;
            float w = 0.f;
            for (int jj = 0; jj < 8; jj++) {
                float m = (l == 0) ? We1[k * 8 + jj] : (l == 1 ? M2[k * 8 + jj] : M3[k * 8 + jj]);
                w += m * ae[jj];
            }
            g_w[l][k] = w;
        }
        if (t < 3) {
            const float* ae = (t == 0 ? att1 : (t == 1 ? att2 : att3)) + 64;
            const float* c = (t == 0 ? c1 : (t == 1 ? c2 : c3));
            float d = 0.f;
            for (int jj = 0; jj < 8; jj++) d += c[jj] * ae[jj];
            g_d[t] = d;
        }
        for (int idx = t; idx < GG * HH; idx += blockDim.x) g_pool[idx] = 0.f;
        if (t < GG) g_cnt[t] = 0.f;
    }

    int t4 = blockIdx.x * blockDim.x + threadIdx.x;
    if (t4 * 4 >= EE) return;
    int d[4];
    if (is64) {
        const longlong4* p = (const longlong4*)((const long long*)eidxv + EE);
        longlong4 q = p[t4];
        d[0] = (int)q.x; d[1] = (int)q.y; d[2] = (int)q.z; d[3] = (int)q.w;
    } else {
        const int4* p = (const int4*)((const int*)eidxv + EE);
        int4 q = p[t4];
        d[0] = q.x; d[1] = q.y; d[2] = q.z; d[3] = q.w;
    }
#pragma unroll
    for (int i = 0; i < 4; i++) {
        int dn = min(max(d[i], 0), NN - 1);
        atomicAdd(&g_deg[dn], 1);
    }
}

// ---------------- scanA: per-1024-chunk sums ----------------
__global__ void scanA_kernel() {
    __shared__ int sh[32];
    int i = blockIdx.x * 1024 + threadIdx.x;
    int v = (i < NN) ? g_deg[i] : 0;
#pragma unroll
    for (int off = 16; off > 0; off >>= 1) v += __shfl_down_sync(0xffffffffu, v, off);
    if ((threadIdx.x & 31) == 0) sh[threadIdx.x >> 5] = v;
    __syncthreads();
    if (threadIdx.x < 32) {
        int x = sh[threadIdx.x];
#pragma unroll
        for (int off = 16; off > 0; off >>= 1) x += __shfl_down_sync(0xffffffffu, x, off);
        if (threadIdx.x == 0) g_bsum[blockIdx.x] = x;
    }
}

// ---------------- scanC: local scan + inline block-offset reduction ----------------
__global__ void scanC_kernel() {
    __shared__ int wsum[32];
    __shared__ int sred[2];
    int tid = threadIdx.x;
    int lane = tid & 31, wid = tid >> 5;
    if (tid < 64) {
        int v = (tid < blockIdx.x && tid < NB) ? g_bsum[tid] : 0;
#pragma unroll
        for (int off = 16; off > 0; off >>= 1) v += __shfl_down_sync(0xffffffffu, v, off);
        if ((tid & 31) == 0) sred[tid >> 5] = v;
    }
    int i = blockIdx.x * 1024 + tid;
    int v = (i < NN) ? g_deg[i] : 0;
    int incl = v;
#pragma unroll
    for (int off = 1; off < 32; off <<= 1) {
        int x = __shfl_up_sync(0xffffffffu, incl, off);
        if (lane >= off) incl += x;
    }
    if (lane == 31) wsum[wid] = incl;
    __syncthreads();
    if (wid == 0) {
        int x = wsum[lane];
        int xi = x;
#pragma unroll
        for (int off = 1; off < 32; off <<= 1) {
            int y = __shfl_up_sync(0xffffffffu, xi, off);
            if (lane >= off) xi += y;
        }
        wsum[lane] = xi - x;
    }
    __syncthreads();
    int excl = incl - v + wsum[wid] + sred[0] + sred[1];
    if (i < NN) { g_rowptr[i] = excl; g_cursor[i] = excl; }
    if (i == 0) g_rowptr[NN] = EE;
}

// ---------------- fused eterm + scatter: 2 edges/thread, high occupancy ----------------
__global__ void __launch_bounds__(256, 6)
scatter_fused_kernel(const void* __restrict__ eidxv, const float* __restrict__ ea) {
    int is64 = block_is64((const int*)eidxv);
    int t = blockIdx.x * blockDim.x + threadIdx.x;
    if (t * 2 >= EE) return;
    int sn[2], dn[2];
    if (is64) {
        const longlong2* ps = (const longlong2*)eidxv;
        const longlong2* pd = (const longlong2*)((const long long*)eidxv + EE);
        longlong2 qs = ps[t], qd = pd[t];
        sn[0] = (int)qs.x; sn[1] = (int)qs.y;
        dn[0] = (int)qd.x; dn[1] = (int)qd.y;
    } else {
        const int2* ps = (const int2*)eidxv;
        const int2* pd = (const int2*)((const int*)eidxv + EE);
        int2 qs = ps[t], qd = pd[t];
        sn[0] = qs.x; sn[1] = qs.y;
        dn[0] = qd.x; dn[1] = qd.y;
    }
    const float4* ea4 = (const float4*)ea;
    uint2 pay[2];
#pragma unroll
    for (int k = 0; k < 2; k++) {
        int e = t * 2 + k;
        unsigned s = (unsigned)min(max(sn[k], 0), NN - 1);
        float4 a0 = ea4[e * 2];
        float4 a1 = ea4[e * 2 + 1];
        float et[3];
#pragma unroll
        for (int l = 0; l < 3; l++) {
            const float* w = g_w[l];
            et[l] = g_d[l]
                  + a0.x * w[0] + a0.y * w[1] + a0.z * w[2] + a0.w * w[3]
                  + a1.x * w[4] + a1.y * w[5] + a1.z * w[6] + a1.w * w[7];
        }
        unsigned h0 = (unsigned)__half_as_ushort(__float2half_rn(et[0]));
        unsigned h1 = (unsigned)__half_as_ushort(__float2half_rn(et[1]));
        unsigned h2 = (unsigned)__half_as_ushort(__float2half_rn(et[2]));
        pay[k].x = s | (h0 << 16);
        pay[k].y = h1 | (h2 << 16);
    }
    int pos[2];
#pragma unroll
    for (int k = 0; k < 2; k++) {
        int d = min(max(dn[k], 0), NN - 1);
        pos[k] = atomicAdd(&g_cursor[d], 1);
    }
#pragma unroll
    for (int k = 0; k < 2; k++) g_csr[pos[k]] = pay[k];
}

// ---------------- node linear: smem-staged input, fp16 xn output ----------------
template <int IN, bool RELU, bool FROM_GOUT>
__global__ void node_linear_kernel(const float* __restrict__ xin_ext,
                                   const float* __restrict__ W,
                                   const float* __restrict__ b,
                                   const float* __restrict__ att) {
    __shared__ float sW[IN * HH];
    __shared__ float sb[HH];
    __shared__ float sA[64];
    __shared__ float sX[256 * (IN + 1)];
    int tid = threadIdx.x;
    for (int i = tid; i < IN * HH; i += blockDim.x) sW[i] = W[i];
    if (tid < HH) sb[tid] = b[tid];
    if (tid < 64) sA[tid] = att[tid];
    int base = blockIdx.x * 256;
    int nvalid = min(256, NN - base);
    const float* src = FROM_GOUT ? g_out : xin_ext;
    for (int i = tid; i < nvalid * IN; i += 256) {
        int nl = i / IN;
        int k = i - nl * IN;
        sX[nl * (IN + 1) + k] = src[(size_t)base * IN + i];
    }
    __syncthreads();
    int node = base + tid;
    if (tid >= nvalid) return;
    const float* xr = sX + tid * (IN + 1);
    float acc[HH];
#pragma unroll
    for (int h = 0; h < HH; h++) acc[h] = sb[h];
#pragma unroll
    for (int k = 0; k < IN; k++) {
        float xv = xr[k];
        if (RELU) xv = fmaxf(xv, 0.f);
#pragma unroll
        for (int h = 0; h < HH; h++) acc[h] = fmaf(xv, sW[k * HH + h], acc[h]);
    }
    uint4* o = (uint4*)(g_xnh + (size_t)node * 16);
#pragma unroll
    for (int q = 0; q < 4; q++) {
        uint4 pk;
        __half2 h0 = __floats2half2_rn(acc[8 * q + 0], acc[8 * q + 1]);
        __half2 h1 = __floats2half2_rn(acc[8 * q + 2], acc[8 * q + 3]);
        __half2 h2 = __floats2half2_rn(acc[8 * q + 4], acc[8 * q + 5]);
        __half2 h3 = __floats2half2_rn(acc[8 * q + 6], acc[8 * q + 7]);
        pk.x = *(unsigned*)&h0; pk.y = *(unsigned*)&h1;
        pk.z = *(unsigned*)&h2; pk.w = *(unsigned*)&h3;
        o[q] = pk;
    }
    float u = 0.f, v = 0.f;
#pragma unroll
    for (int h = 0; h < HH; h++) {
        u = fmaf(acc[h], sA[h], u);
        v = fmaf(acc[h], sA[h + 32], v);
    }
    g_u[node] = u;
    g_v[node] = v;
}

// ---------------- fused softmax + aggregate: one warp per dst node ----------------
// Phase 1: 32 lanes compute p for 32 edges, stage {sn,p} in smem.
// Phase 2: 4-deep prefetch — load all 4 row-slices per 4-lane group, then FMA.
template <int L>
__global__ void edge_fused_kernel() {
    __shared__ __align__(8) float2 sE[8][32];
    int wib = threadIdx.x >> 5;
    int w = (blockIdx.x * blockDim.x + threadIdx.x) >> 5;
    int lane = threadIdx.x & 31;
    if (w >= NN) return;
    int start = g_rowptr[w];
    int end = g_rowptr[w + 1];
    float u = g_u[w];
    int part = lane & 3, grp = lane >> 2;
    float acc[8] = {0.f, 0.f, 0.f, 0.f, 0.f, 0.f, 0.f, 0.f};
    float s = 0.f;
    for (int base = start; base < end; base += 32) {
        int e = base + lane;
        float p = 0.f; int sn = 0;
        if (e < end) {
            uint2 q = g_csr[e];
            sn = (int)(q.x & 0xffffu);
            unsigned hb = (L == 0) ? (q.x >> 16) : (L == 1) ? (q.y & 0xffffu) : (q.y >> 16);
            float et = __half2float(__ushort_as_half((unsigned short)hb));
            float lg = u + g_v[sn] + et;
            lg = (lg > 0.f) ? lg : NEG_SLOPE * lg;
            p = __expf(lg);
        }
        sE[wib][lane] = make_float2(__int_as_float(sn), p);
        __syncwarp();
        int cnt = min(32, end - base);
        // 4-deep prefetch: load rows for j = grp, grp+8, grp+16, grp+24
        float pj[4];
        uint4 rvj[4];
#pragma unroll
        for (int it = 0; it < 4; it++) {
            int j = grp + it * 8;
            if (j < cnt) {
                float2 sp = sE[wib][j];
                pj[it] = sp.y;
                rvj[it] = ((const uint4*)(g_xnh + (size_t)__float_as_int(sp.x) * 16))[part];
            } else {
                pj[it] = 0.f;
                rvj[it] = make_uint4(0u, 0u, 0u, 0u);
            }
        }
#pragma unroll
        for (int it = 0; it < 4; it++) {
            float pp = pj[it];
            uint4 rv = rvj[it];
            float2 f0 = __half22float2(*(__half2*)&rv.x);
            float2 f1 = __half22float2(*(__half2*)&rv.y);
            float2 f2 = __half22float2(*(__half2*)&rv.z);
            float2 f3 = __half22float2(*(__half2*)&rv.w);
            acc[0] = fmaf(pp, f0.x, acc[0]);
            acc[1] = fmaf(pp, f0.y, acc[1]);
            acc[2] = fmaf(pp, f1.x, acc[2]);
            acc[3] = fmaf(pp, f1.y, acc[3]);
            acc[4] = fmaf(pp, f2.x, acc[4]);
            acc[5] = fmaf(pp, f2.y, acc[5]);
            acc[6] = fmaf(pp, f3.x, acc[6]);
            acc[7] = fmaf(pp, f3.y, acc[7]);
            s += pp;
        }
        __syncwarp();
    }
#pragma unroll
    for (int off = 16; off >= 4; off >>= 1) {
#pragma unroll
        for (int i = 0; i < 8; i++) acc[i] += __shfl_down_sync(0xffffffffu, acc[i], off);
        s += __shfl_down_sync(0xffffffffu, s, off);
    }
    if (grp == 0) {
        float inv = 1.f / (s + 1e-16f);
        float4* o = (float4*)(g_out + (size_t)w * HH);
        o[part * 2]     = make_float4(acc[0] * inv, acc[1] * inv, acc[2] * inv, acc[3] * inv);
        o[part * 2 + 1] = make_float4(acc[4] * inv, acc[5] * inv, acc[6] * inv, acc[7] * inv);
    }
}

// ---------------- mean pool over sorted batch; re-zero g_deg for next call ----------------
__global__ void pool_kernel(const void* __restrict__ batchv, const int* __restrict__ eidx_words) {
    int is64 = block_is64(eidx_words);
    int gtid = blockIdx.x * blockDim.x + threadIdx.x;
    if (gtid < NN) g_deg[gtid] = 0;
    int w = gtid >> 5;
    int lane = threadIdx.x & 31;
    int base = w * 32;
    if (base >= NN) return;
    int nmax = min(32, NN - base);
    int myb = 0;
    if (lane < nmax) {
        if (is64) myb = (int)((const long long*)batchv)[base + lane];
        else      myb = ((const int*)batchv)[base + lane];
        myb = min(max(myb, 0), GG - 1);
    }
    float acc = 0.f, cnt = 0.f;
    int curb = __shfl_sync(0xffffffffu, myb, 0);
    for (int n = 0; n < nmax; n++) {
        int b = __shfl_sync(0xffffffffu, myb, n);
        if (b != curb) {
            atomicAdd(&g_pool[curb * HH + lane], acc);
            if (lane == 0) atomicAdd(&g_cnt[curb], cnt);
            acc = 0.f; cnt = 0.f; curb = b;
        }
        acc += g_out[(size_t)(base + n) * HH + lane];
        cnt += 1.f;
    }
    atomicAdd(&g_pool[curb * HH + lane], acc);
    if (lane == 0) atomicAdd(&g_cnt[curb], cnt);
}

// ---------------- head ----------------
__global__ void head_kernel(const float* __restrict__ Wlin, const float* __restrict__ blin,
                            float* __restrict__ out) {
    int g = threadIdx.x >> 5;
    int lane = threadIdx.x & 31;
    if (g >= GG) return;
    float v = g_pool[g * HH + lane] * Wlin[lane];
#pragma unroll
    for (int o = 16; o > 0; o >>= 1) v += __shfl_xor_sync(0xffffffffu, v, o);
    if (lane == 0) out[g] = v / fmaxf(g_cnt[g], 1.f) + blin[0];
}

// ---------------- launch ----------------
extern "C" void kernel_launch(void* const* d_in, const int* in_sizes, int n_in,
                              void* d_out, int out_size) {
    const float* x     = (const float*)d_in[0];
    const float* ea    = (const float*)d_in[1];
    const void*  eidx  = d_in[2];
    const void*  batch = d_in[3];
    const float *Wn1 = (const float*)d_in[4],  *bn1 = (const float*)d_in[5];
    const float *We1 = (const float*)d_in[6],  *be1 = (const float*)d_in[7],  *att1 = (const float*)d_in[8];
    const float *Wn2 = (const float*)d_in[9],  *bn2 = (const float*)d_in[10];
    const float *We2 = (const float*)d_in[11], *be2 = (const float*)d_in[12], *att2 = (const float*)d_in[13];
    const float *Wn3 = (const float*)d_in[14], *bn3 = (const float*)d_in[15];
    const float *We3 = (const float*)d_in[16], *be3 = (const float*)d_in[17], *att3 = (const float*)d_in[18];
    const float *Wlin = (const float*)d_in[19], *blin = (const float*)d_in[20];
    float* out = (float*)d_out;

    const int NODE_BLOCKS = (NN + 255) / 256;
    const int WARP_BLOCKS = (NN * 32 + 255) / 256;

    deg_prep_kernel<<<(EE / 4 + 255) / 256, 256>>>(eidx,
        We1, be1, att1, We2, be2, att2, We3, be3, att3);
    scanA_kernel<<<NB, 1024>>>();
    scanC_kernel<<<NB, 1024>>>();
    scatter_fused_kernel<<<(EE / 2 + 255) / 256, 256>>>(eidx, ea);

    // layer 1
    node_linear_kernel<16, false, false><<<NODE_BLOCKS, 256>>>(x, Wn1, bn1, att1);
    edge_fused_kernel<0><<<WARP_BLOCKS, 256>>>();
    // layer 2
    node_linear_kernel<32, true, true><<<NODE_BLOCKS, 256>>>(nullptr, Wn2, bn2, att2);
    edge_fused_kernel<1><<<WARP_BLOCKS, 256>>>();
    // layer 3
    node_linear_kernel<32, true, true><<<NODE_BLOCKS, 256>>>(nullptr, Wn3, bn3, att3);
    edge_fused_kernel<2><<<WARP_BLOCKS, 256>>>();

    // pooling + head
    pool_kernel<<<NODE_BLOCKS, 256>>>(batch, (const int*)eidx);
    head_kernel<<<1, 512>>>(Wlin, blin, out);
}